// round 4
// baseline (speedup 1.0000x reference)
#include <cuda_runtime.h>
#include <cuda_bf16.h>
#include <cfloat>
#include <math.h>
#include <stdint.h>

// Problem constants
#define BATCH 2
#define SEQ 1024
#define HID 4096
#define NH 32
#define KVH 8
#define HD 128
#define ROWS (BATCH*SEQ)          // 2048
#define KVDIM (KVH*HD)            // 1024

// ---------------- scratch (static __device__, no allocation) ----------------
__device__ float g_Q[ROWS * HID];     // (b,s,32,128)
__device__ float g_K[ROWS * KVDIM];   // (b,s,8,128)
__device__ float g_V[ROWS * KVDIM];
__device__ float g_A[ROWS * HID];     // attention output (b,s,32,128)

// ---------------- fp32 SGEMM body: C[M,N] = A[M,K] * B[N,K]^T (NT) ----------
// 128x128 tile, TBK=16, 256 threads, 8x8 per thread.
// Two-stage smem double buffer: one barrier per k-tile, full-window prefetch.
#define TBM 128
#define TBN 128
#define TBK 16

__device__ __forceinline__ void gemm128(const float* __restrict__ A,
                                        const float* __restrict__ B,
                                        float* __restrict__ C,
                                        int N, int K, int bx, int by)
{
    __shared__ float As[2][TBK][TBM];
    __shared__ float Bs[2][TBK][TBN];
    int tid  = threadIdx.x;
    int lrow = tid >> 1;             // 0..127
    int lcol = (tid & 1) * 8;        // 0 or 8
    const float* Ap = A + (size_t)(by * TBM + lrow) * K + lcol;
    const float* Bp = B + (size_t)(bx * TBN + lrow) * K + lcol;

    // preload k-tile 0
    float4 pa0 = *(const float4*)(Ap);
    float4 pa1 = *(const float4*)(Ap + 4);
    float4 pb0 = *(const float4*)(Bp);
    float4 pb1 = *(const float4*)(Bp + 4);
    As[0][lcol + 0][lrow] = pa0.x; As[0][lcol + 1][lrow] = pa0.y;
    As[0][lcol + 2][lrow] = pa0.z; As[0][lcol + 3][lrow] = pa0.w;
    As[0][lcol + 4][lrow] = pa1.x; As[0][lcol + 5][lrow] = pa1.y;
    As[0][lcol + 6][lrow] = pa1.z; As[0][lcol + 7][lrow] = pa1.w;
    Bs[0][lcol + 0][lrow] = pb0.x; Bs[0][lcol + 1][lrow] = pb0.y;
    Bs[0][lcol + 2][lrow] = pb0.z; Bs[0][lcol + 3][lrow] = pb0.w;
    Bs[0][lcol + 4][lrow] = pb1.x; Bs[0][lcol + 5][lrow] = pb1.y;
    Bs[0][lcol + 6][lrow] = pb1.z; Bs[0][lcol + 7][lrow] = pb1.w;
    __syncthreads();

    int tx = tid & 15, ty = tid >> 4;
    float acc[8][8];
#pragma unroll
    for (int i = 0; i < 8; i++)
#pragma unroll
        for (int j = 0; j < 8; j++) acc[i][j] = 0.f;

    int buf = 0;
    for (int k0 = 0; k0 < K; k0 += TBK) {
        bool more = (k0 + TBK) < K;
        if (more) {   // prefetch next tile into registers (overlaps compute below)
            pa0 = *(const float4*)(Ap + k0 + TBK);
            pa1 = *(const float4*)(Ap + k0 + TBK + 4);
            pb0 = *(const float4*)(Bp + k0 + TBK);
            pb1 = *(const float4*)(Bp + k0 + TBK + 4);
        }
#pragma unroll
        for (int kk = 0; kk < TBK; kk++) {
            float4 a0 = *(const float4*)&As[buf][kk][ty * 8];
            float4 a1 = *(const float4*)&As[buf][kk][ty * 8 + 4];
            float4 b0 = *(const float4*)&Bs[buf][kk][tx * 8];
            float4 b1 = *(const float4*)&Bs[buf][kk][tx * 8 + 4];
            float ar[8] = {a0.x, a0.y, a0.z, a0.w, a1.x, a1.y, a1.z, a1.w};
            float br[8] = {b0.x, b0.y, b0.z, b0.w, b1.x, b1.y, b1.z, b1.w};
#pragma unroll
            for (int i = 0; i < 8; i++)
#pragma unroll
                for (int j = 0; j < 8; j++)
                    acc[i][j] = fmaf(ar[i], br[j], acc[i][j]);
        }
        if (more) {   // write prefetched tile into the other buffer
            int nb = buf ^ 1;
            As[nb][lcol + 0][lrow] = pa0.x; As[nb][lcol + 1][lrow] = pa0.y;
            As[nb][lcol + 2][lrow] = pa0.z; As[nb][lcol + 3][lrow] = pa0.w;
            As[nb][lcol + 4][lrow] = pa1.x; As[nb][lcol + 5][lrow] = pa1.y;
            As[nb][lcol + 6][lrow] = pa1.z; As[nb][lcol + 7][lrow] = pa1.w;
            Bs[nb][lcol + 0][lrow] = pb0.x; Bs[nb][lcol + 1][lrow] = pb0.y;
            Bs[nb][lcol + 2][lrow] = pb0.z; Bs[nb][lcol + 3][lrow] = pb0.w;
            Bs[nb][lcol + 4][lrow] = pb1.x; Bs[nb][lcol + 5][lrow] = pb1.y;
            Bs[nb][lcol + 6][lrow] = pb1.z; Bs[nb][lcol + 7][lrow] = pb1.w;
            __syncthreads();
        }
        buf ^= 1;
    }
    float* Cp = C + (size_t)(by * TBM + ty * 8) * N + bx * TBN + tx * 8;
#pragma unroll
    for (int i = 0; i < 8; i++) {
        *(float4*)(Cp + (size_t)i * N)     = make_float4(acc[i][0], acc[i][1], acc[i][2], acc[i][3]);
        *(float4*)(Cp + (size_t)i * N + 4) = make_float4(acc[i][4], acc[i][5], acc[i][6], acc[i][7]);
    }
}

// Fused QKV projection: grid.x 0..47 -> 32 Q blocks, 8 K blocks, 8 V blocks
__global__ __launch_bounds__(256) void qkv_gemm(const float* __restrict__ X,
                                                const float* __restrict__ Wq,
                                                const float* __restrict__ Wk,
                                                const float* __restrict__ Wv,
                                                float* __restrict__ Qo,
                                                float* __restrict__ Ko,
                                                float* __restrict__ Vo)
{
    int bx = blockIdx.x;
    const float* Bsel;
    float* Csel;
    int N, cb;
    if (bx < 32)      { Bsel = Wq; Csel = Qo; N = HID;   cb = bx; }
    else if (bx < 40) { Bsel = Wk; Csel = Ko; N = KVDIM; cb = bx - 32; }
    else              { Bsel = Wv; Csel = Vo; N = KVDIM; cb = bx - 40; }
    gemm128(X, Bsel, Csel, N, HID, cb, blockIdx.y);
}

__global__ __launch_bounds__(256) void o_gemm(const float* __restrict__ A,
                                              const float* __restrict__ Wo,
                                              float* __restrict__ C)
{
    gemm128(A, Wo, C, HID, HID, blockIdx.x, blockIdx.y);
}

// ---------------- fake_quant_sparse: K (per-column, n=2048) -----------------
// exact order stats via in-smem bitonic sort (matches jnp.quantile 'linear').
// maxval/minval/median are exact data values; interpolated thresholds only
// gate the mask and sit strictly inside sort gaps -> quant params are
// data-determined. Only round() boundary flips from GEMM epsilon remain.
__global__ __launch_bounds__(256) void quant_k_cols(float* __restrict__ Kd)
{
    const int n = 2048;
    __shared__ float s[2048];
    __shared__ float red[256];
    int col = blockIdx.x;
    int tid = threadIdx.x;
    float vals[8];
#pragma unroll
    for (int i = 0; i < 8; i++) {
        float v = Kd[(size_t)(i * 256 + tid) * KVDIM + col];
        vals[i] = v;
        s[i * 256 + tid] = v;
    }
    __syncthreads();
    // bitonic sort ascending
    for (int k = 2; k <= n; k <<= 1) {
        for (int j = k >> 1; j > 0; j >>= 1) {
            for (int t = tid; t < n; t += 256) {
                int ixj = t ^ j;
                if (ixj > t) {
                    float a = s[t], b = s[ixj];
                    bool up = ((t & k) == 0);
                    if ((a > b) == up) { s[t] = b; s[ixj] = a; }
                }
            }
            __syncthreads();
        }
    }
    // order statistics (jnp.quantile linear interp), t = 0.9995
    float tq = 1.0f - (1.0f - 0.999f) / 2.0f;
    float plo = (1.0f - tq) * (n - 1);
    float phi = tq * (n - 1);
    int ilo = (int)plo, ihi = (int)phi;
    float flo = plo - ilo, fhi = phi - ihi;
    float lower = s[ilo] + flo * (s[ilo + 1] - s[ilo]);
    float upper = s[ihi] + fhi * (s[ihi + 1] - s[ihi]);
    float med = s[(n - 1) / 2];
    // min/max of tmp (= x with outliers replaced by med)
    float mn = FLT_MAX, mx = -FLT_MAX;
#pragma unroll
    for (int i = 0; i < 8; i++) {
        float x = vals[i];
        bool mask = (x <= lower) || (x >= upper);
        float tv = mask ? med : x;
        mn = fminf(mn, tv);
        mx = fmaxf(mx, tv);
    }
    red[tid] = mn; __syncthreads();
    for (int off = 128; off; off >>= 1) {
        if (tid < off) red[tid] = fminf(red[tid], red[tid + off]);
        __syncthreads();
    }
    mn = red[0]; __syncthreads();
    red[tid] = mx; __syncthreads();
    for (int off = 128; off; off >>= 1) {
        if (tid < off) red[tid] = fmaxf(red[tid], red[tid + off]);
        __syncthreads();
    }
    mx = red[0];
    float qx = 15.0f / (mx - mn);
    float offn = mn * qx;
#pragma unroll
    for (int i = 0; i < 8; i++) {
        float x = vals[i];
        bool mask = (x <= lower) || (x >= upper);
        float out;
        if (mask) out = x;
        else {
            float q = rintf(qx * x - offn);     // round-half-to-even == jnp.round
            q = fminf(fmaxf(q, 0.f), 15.f);
            out = (q + offn) / qx;
        }
        if (!isfinite(out)) out = 0.f;
        Kd[(size_t)(i * 256 + tid) * KVDIM + col] = out;
    }
}

// ---------------- fake_quant_sparse: V (per-row, n=1024) --------------------
__global__ __launch_bounds__(256) void quant_v_rows(float* __restrict__ Vd)
{
    const int n = 1024;
    __shared__ float s[1024];
    __shared__ float red[256];
    int row = blockIdx.x;
    int tid = threadIdx.x;
    float* rp = Vd + (size_t)row * KVDIM;
    float vals[4];
#pragma unroll
    for (int i = 0; i < 4; i++) {
        float v = rp[i * 256 + tid];
        vals[i] = v;
        s[i * 256 + tid] = v;
    }
    __syncthreads();
    for (int k = 2; k <= n; k <<= 1) {
        for (int j = k >> 1; j > 0; j >>= 1) {
            for (int t = tid; t < n; t += 256) {
                int ixj = t ^ j;
                if (ixj > t) {
                    float a = s[t], b = s[ixj];
                    bool up = ((t & k) == 0);
                    if ((a > b) == up) { s[t] = b; s[ixj] = a; }
                }
            }
            __syncthreads();
        }
    }
    float tq = 1.0f - (1.0f - 0.999f) / 2.0f;
    float plo = (1.0f - tq) * (n - 1);
    float phi = tq * (n - 1);
    int ilo = (int)plo, ihi = (int)phi;
    float flo = plo - ilo, fhi = phi - ihi;
    float lower = s[ilo] + flo * (s[ilo + 1] - s[ilo]);
    float upper = s[ihi] + fhi * (s[ihi + 1] - s[ihi]);
    float med = s[(n - 1) / 2];
    float mn = FLT_MAX, mx = -FLT_MAX;
#pragma unroll
    for (int i = 0; i < 4; i++) {
        float x = vals[i];
        bool mask = (x <= lower) || (x >= upper);
        float tv = mask ? med : x;
        mn = fminf(mn, tv);
        mx = fmaxf(mx, tv);
    }
    red[tid] = mn; __syncthreads();
    for (int off = 128; off; off >>= 1) {
        if (tid < off) red[tid] = fminf(red[tid], red[tid + off]);
        __syncthreads();
    }
    mn = red[0]; __syncthreads();
    red[tid] = mx; __syncthreads();
    for (int off = 128; off; off >>= 1) {
        if (tid < off) red[tid] = fmaxf(red[tid], red[tid + off]);
        __syncthreads();
    }
    mx = red[0];
    float qx = 15.0f / (mx - mn);
    float offn = mn * qx;
#pragma unroll
    for (int i = 0; i < 4; i++) {
        float x = vals[i];
        bool mask = (x <= lower) || (x >= upper);
        float out;
        if (mask) out = x;
        else {
            float q = rintf(qx * x - offn);
            q = fminf(fmaxf(q, 0.f), 15.f);
            out = (q + offn) / qx;
        }
        if (!isfinite(out)) out = 0.f;
        rp[i * 256 + tid] = out;
    }
}

// ---------------- RoPE (layout (b,s,h,128), positions = arange(S)) ----------
// Fast-math-proof: inv_freq via double exp/log (powf may be demoted to
// __powf by --use_fast_math, 1e-5 rel -> 1e-2 rad phase error at pos 1023);
// trig args range-reduced mod 2pi in double so cosf/sinf (fast or precise)
// see |r| <= pi where both are ~2^-21-accurate.
__global__ void rope_kernel(float* __restrict__ X, int nheads)
{
    int idx = blockIdx.x * blockDim.x + threadIdx.x;
    int total = BATCH * SEQ * nheads * 64;
    if (idx >= total) return;
    int i = idx & 63;
    int rest = idx >> 6;                       // (b*SEQ + s)*nheads + h
    int sh = rest / nheads;                    // b*SEQ + s
    int spos = sh & (SEQ - 1);
    double expo = (double)(2 * i) / 128.0;
    float invf = (float)exp(-expo * 9.210340371976184);   // ln(10000)
    float f = (float)spos * invf;                          // fp32, as reference
    double fd = (double)f;
    double r = fd - rint(fd * 0.15915494309189535) * 6.283185307179586;
    float rf = (float)r;
    float c = cosf(rf), sn = sinf(rf);
    size_t base = (size_t)rest * 128 + i;
    float lo = X[base], hi = X[base + 64];
    X[base]      = lo * c - hi * sn;
    X[base + 64] = hi * c + lo * sn;
}

// ---------------- causal flash attention, fp32 ------------------------------
// grid (16 qtiles, 32 heads, 2 batch), 256 threads, 64x64 tiles, D=128
#define QST 68   // padded smem stride (floats), 16B-aligned rows

#define ATTN_SMEM ((128*QST + 128*QST + 64*128 + 64*QST) * 4)

__global__ __launch_bounds__(256) void attn_kernel(const float* __restrict__ Q,
                                                   const float* __restrict__ Km,
                                                   const float* __restrict__ Vm,
                                                   float* __restrict__ O)
{
    extern __shared__ float smb[];
    float* Qst = smb;                    // [128][QST]  Q^T tile
    float* Kst = Qst + 128 * QST;        // [128][QST]  K^T tile
    float* Vs  = Kst + 128 * QST;        // [64][128]
    float* Sst = Vs + 64 * 128;          // [64][QST]   P^T tile
    // heavy (late) q-tiles first: better wave packing under causal imbalance
    int qt = (SEQ / 64 - 1) - blockIdx.x;
    int h = blockIdx.y, b = blockIdx.z;
    int kvh = h >> 2;                    // groups = 4
    int tid = threadIdx.x;
    int tx = tid & 15, ty = tid >> 4;
    int q0 = qt * 64;

    // load Q tile transposed
    for (int t = tid; t < 64 * 32; t += 256) {
        int rr = t >> 5, cc = (t & 31) << 2;
        float4 v = *(const float4*)&Q[(((size_t)(b * SEQ + q0 + rr)) * NH + h) * HD + cc];
        Qst[(cc + 0) * QST + rr] = v.x;
        Qst[(cc + 1) * QST + rr] = v.y;
        Qst[(cc + 2) * QST + rr] = v.z;
        Qst[(cc + 3) * QST + rr] = v.w;
    }

    float m_run[4], l_run[4], acc[4][8];
#pragma unroll
    for (int i = 0; i < 4; i++) {
        m_run[i] = -FLT_MAX; l_run[i] = 0.f;
#pragma unroll
        for (int j = 0; j < 8; j++) acc[i][j] = 0.f;
    }
    const float scale = 0.08838834764831845f;   // 1/sqrt(128)

    for (int jt = 0; jt <= qt; jt++) {
        int k0 = jt * 64;
        __syncthreads();
        for (int t = tid; t < 64 * 32; t += 256) {
            int rr = t >> 5, cc = (t & 31) << 2;
            size_t gi = (((size_t)(b * SEQ + k0 + rr)) * KVH + kvh) * HD + cc;
            float4 kv = *(const float4*)&Km[gi];
            Kst[(cc + 0) * QST + rr] = kv.x;
            Kst[(cc + 1) * QST + rr] = kv.y;
            Kst[(cc + 2) * QST + rr] = kv.z;
            Kst[(cc + 3) * QST + rr] = kv.w;
            *(float4*)&Vs[rr * 128 + cc] = *(const float4*)&Vm[gi];
        }
        __syncthreads();

        // scores: 4x4 per thread
        float s4[4][4];
#pragma unroll
        for (int i = 0; i < 4; i++)
#pragma unroll
            for (int j = 0; j < 4; j++) s4[i][j] = 0.f;
#pragma unroll 4
        for (int d = 0; d < 128; d++) {
            float4 qv = *(const float4*)&Qst[d * QST + ty * 4];
            float4 kv = *(const float4*)&Kst[d * QST + tx * 4];
            float qa[4] = {qv.x, qv.y, qv.z, qv.w};
            float ka[4] = {kv.x, kv.y, kv.z, kv.w};
#pragma unroll
            for (int i = 0; i < 4; i++)
#pragma unroll
                for (int j = 0; j < 4; j++)
                    s4[i][j] = fmaf(qa[i], ka[j], s4[i][j]);
        }
        // scale + causal mask
#pragma unroll
        for (int i = 0; i < 4; i++) {
            int qi = q0 + ty * 4 + i;
#pragma unroll
            for (int j = 0; j < 4; j++) {
                int kj = k0 + tx * 4 + j;
                float sv = s4[i][j] * scale;
                s4[i][j] = (kj > qi) ? -FLT_MAX : sv;
            }
        }
        // online softmax per row (rows owned by 16-lane groups)
#pragma unroll
        for (int i = 0; i < 4; i++) {
            float mloc = fmaxf(fmaxf(s4[i][0], s4[i][1]), fmaxf(s4[i][2], s4[i][3]));
            mloc = fmaxf(mloc, __shfl_xor_sync(0xffffffffu, mloc, 8, 16));
            mloc = fmaxf(mloc, __shfl_xor_sync(0xffffffffu, mloc, 4, 16));
            mloc = fmaxf(mloc, __shfl_xor_sync(0xffffffffu, mloc, 2, 16));
            mloc = fmaxf(mloc, __shfl_xor_sync(0xffffffffu, mloc, 1, 16));
            float mn = fmaxf(m_run[i], mloc);
            float corr = expf(m_run[i] - mn);
            m_run[i] = mn;
            float sloc = 0.f;
#pragma unroll
            for (int j = 0; j < 4; j++) {
                float p = expf(s4[i][j] - mn);
                s4[i][j] = p;
                sloc += p;
            }
            sloc += __shfl_xor_sync(0xffffffffu, sloc, 8, 16);
            sloc += __shfl_xor_sync(0xffffffffu, sloc, 4, 16);
            sloc += __shfl_xor_sync(0xffffffffu, sloc, 2, 16);
            sloc += __shfl_xor_sync(0xffffffffu, sloc, 1, 16);
            l_run[i] = l_run[i] * corr + sloc;
#pragma unroll
            for (int j = 0; j < 8; j++) acc[i][j] *= corr;
        }
        // store P transposed
#pragma unroll
        for (int i = 0; i < 4; i++)
#pragma unroll
            for (int j = 0; j < 4; j++)
                Sst[(tx * 4 + j) * QST + (ty * 4 + i)] = s4[i][j];
        __syncthreads();
        // PV: rows ty*4..+4, dims tx*8..+8
#pragma unroll 2
        for (int c = 0; c < 64; c++) {
            float4 pv = *(const float4*)&Sst[c * QST + ty * 4];
            float4 v0 = *(const float4*)&Vs[c * 128 + tx * 8];
            float4 v1 = *(const float4*)&Vs[c * 128 + tx * 8 + 4];
            float p[4] = {pv.x, pv.y, pv.z, pv.w};
            float vv[8] = {v0.x, v0.y, v0.z, v0.w, v1.x, v1.y, v1.z, v1.w};
#pragma unroll
            for (int i = 0; i < 4; i++)
#pragma unroll
                for (int j = 0; j < 8; j++)
                    acc[i][j] = fmaf(p[i], vv[j], acc[i][j]);
        }
    }
    // epilogue
#pragma unroll
    for (int i = 0; i < 4; i++) {
        float inv = 1.0f / l_run[i];
        int row = q0 + ty * 4 + i;
        float* op = O + (((size_t)(b * SEQ + row)) * NH + h) * HD + tx * 8;
        *(float4*)op       = make_float4(acc[i][0] * inv, acc[i][1] * inv, acc[i][2] * inv, acc[i][3] * inv);
        *(float4*)(op + 4) = make_float4(acc[i][4] * inv, acc[i][5] * inv, acc[i][6] * inv, acc[i][7] * inv);
    }
}

// ---------------- launch ----------------------------------------------------
extern "C" void kernel_launch(void* const* d_in, const int* in_sizes, int n_in,
                              void* d_out, int out_size)
{
    (void)in_sizes; (void)n_in; (void)out_size;
    const float* X  = (const float*)d_in[0];
    const float* Wq = (const float*)d_in[1];
    const float* Wk = (const float*)d_in[2];
    const float* Wv = (const float*)d_in[3];
    const float* Wo = (const float*)d_in[4];
    float* out = (float*)d_out;

    void *pQ, *pK, *pV, *pA;
    cudaGetSymbolAddress(&pQ, g_Q);
    cudaGetSymbolAddress(&pK, g_K);
    cudaGetSymbolAddress(&pV, g_V);
    cudaGetSymbolAddress(&pA, g_A);

    cudaFuncSetAttribute(attn_kernel, cudaFuncAttributeMaxDynamicSharedMemorySize, ATTN_SMEM);

    qkv_gemm<<<dim3(48, ROWS / TBM), 256>>>(X, Wq, Wk, Wv,
                                            (float*)pQ, (float*)pK, (float*)pV);

    quant_k_cols<<<KVDIM, 256>>>((float*)pK);
    quant_v_rows<<<ROWS, 256>>>((float*)pV);

    rope_kernel<<<(BATCH * SEQ * NH * 64 + 255) / 256, 256>>>((float*)pQ, NH);
    rope_kernel<<<(BATCH * SEQ * KVH * 64 + 255) / 256, 256>>>((float*)pK, KVH);

    attn_kernel<<<dim3(SEQ / 64, NH, BATCH), 256, ATTN_SMEM>>>(
        (const float*)pQ, (const float*)pK, (const float*)pV, (float*)pA);

    o_gemm<<<dim3(HID / TBN, ROWS / TBM), 256>>>((const float*)pA, Wo, out);
}

// round 13
// speedup vs baseline: 1.0480x; 1.0480x over previous
#include <cuda_runtime.h>
#include <cuda_bf16.h>
#include <cfloat>
#include <math.h>
#include <stdint.h>

// Problem constants
#define BATCH 2
#define SEQ 1024
#define HID 4096
#define NH 32
#define KVH 8
#define HD 128
#define ROWS (BATCH*SEQ)          // 2048
#define KVDIM (KVH*HD)            // 1024

// ---------------- scratch (static __device__, no allocation) ----------------
__device__ float g_Q[ROWS * HID];     // (b,s,32,128)
__device__ float g_K[ROWS * KVDIM];
__device__ float g_V[ROWS * KVDIM];
__device__ float g_A[ROWS * HID];     // attention output

// bf16 split operands (full 3-way splits everywhere)
__device__ __nv_bfloat16 sX1[ROWS * HID], sX2[ROWS * HID], sX3[ROWS * HID];
__device__ __nv_bfloat16 sWq1[HID * HID], sWq2[HID * HID], sWq3[HID * HID];
__device__ __nv_bfloat16 sWk1[KVDIM * HID], sWk2[KVDIM * HID], sWk3[KVDIM * HID];
__device__ __nv_bfloat16 sWv1[KVDIM * HID], sWv2[KVDIM * HID], sWv3[KVDIM * HID];
__device__ __nv_bfloat16 sA1[ROWS * HID], sA2[ROWS * HID], sA3[ROWS * HID];
__device__ __nv_bfloat16 sWo1[HID * HID], sWo2[HID * HID], sWo3[HID * HID];

// ---------------- mma.sync helpers (baseline PTX, sm_80+, no 'a' needed) ----
__device__ __forceinline__ uint32_t smem_u32(const void* p) {
    uint32_t a;
    asm("{ .reg .u64 t; cvta.to.shared.u64 t, %1; cvt.u32.u64 %0, t; }"
        : "=r"(a) : "l"(p));
    return a;
}

#define LDSM_X4(r0, r1, r2, r3, addr) \
    asm volatile("ldmatrix.sync.aligned.m8n8.x4.shared.b16 {%0,%1,%2,%3}, [%4];" \
                 : "=r"(r0), "=r"(r1), "=r"(r2), "=r"(r3) : "r"(addr))

__device__ __forceinline__ void mma16816(float* c, const uint32_t* a,
                                         uint32_t b0, uint32_t b1)
{
    asm volatile(
        "mma.sync.aligned.m16n8k16.row.col.f32.bf16.bf16.f32 "
        "{%0,%1,%2,%3}, {%4,%5,%6,%7}, {%8,%9}, {%0,%1,%2,%3};"
        : "+f"(c[0]), "+f"(c[1]), "+f"(c[2]), "+f"(c[3])
        : "r"(a[0]), "r"(a[1]), "r"(a[2]), "r"(a[3]), "r"(b0), "r"(b1));
}

// ---------------- split-bf16 GEMM via mma.sync: C[128,128] = A * B^T --------
// 6 terms: a1b1 + a1b2 + a2b1 + a2b2 + a1b3 + a3b1.
// KEY FIX vs R11/R12: tensor-core accumulators use non-IEEE (RZ/aligned)
// accumulation; long chains cost ~1e-4 rel error. So the TC accumulator is
// drained into a separate fp32 register accumulator (IEEE RN adds) after
// EVERY K-chunk: TC chain length 12 mma steps -> noise back to fp32 class.
#define LDT 40                        // smem tile stride in bf16 (80B, 16B-mult)
#define CH_K 32                       // k per chunk
#define TILE_ELEMS (128 * LDT)        // per tile slot, bf16
#define MMA_SMEM (6 * TILE_ELEMS * 2) // 61440 bytes
#define NTERMS 6

__device__ __forceinline__ void mma_gemm_body(
    const __nv_bfloat16* A1, const __nv_bfloat16* A2, const __nv_bfloat16* A3,
    const __nv_bfloat16* B1, const __nv_bfloat16* B2, const __nv_bfloat16* B3,
    float* C, int ldc, int colbase, int row0, int K)
{
    extern __shared__ __nv_bfloat16 sm[];
    uint32_t smbase = smem_u32(sm);
    int tid = threadIdx.x;
    int wid = tid >> 5, lane = tid & 31;
    int wy = wid >> 1, wx = wid & 1;          // warp tile: rows wy*32, cols wx*64
    const __nv_bfloat16* Ap[3] = {A1, A2, A3};
    const __nv_bfloat16* Bp[3] = {B1, B2, B3};
    const int ta[NTERMS] = {0, 0, 1, 1, 0, 2};
    const int tb[NTERMS] = {0, 1, 0, 1, 2, 0};

    float acc[2][8][4];    // TC accumulator (short chains only)
    float facc[2][8][4];   // fp32 master accumulator (IEEE RN adds)
#pragma unroll
    for (int mt = 0; mt < 2; mt++)
#pragma unroll
        for (int nt = 0; nt < 8; nt++)
#pragma unroll
            for (int e = 0; e < 4; e++) { acc[mt][nt][e] = 0.f; facc[mt][nt][e] = 0.f; }

    // per-lane ldmatrix address components (element units within a tile)
    int a_row = ((lane >> 3) & 1) * 8 + (lane & 7);  // + R
    int a_col = (lane >> 4) * 8;                      // + ks
    int b_row = (lane >> 4) * 8 + (lane & 7);         // + Nb
    int b_col = ((lane >> 3) & 1) * 8;                // + ks

    int nchunks = K / CH_K;
    for (int ch = 0; ch < nchunks; ch++) {
        int k0 = ch * CH_K;
        __syncthreads();                      // previous chunk's compute done
#pragma unroll
        for (int t = 0; t < 3; t++) {
            const __nv_bfloat16* gA = Ap[t];
            const __nv_bfloat16* gB = Bp[t];
            __nv_bfloat16* tA = sm + t * TILE_ELEMS;
            __nv_bfloat16* tB = sm + (3 + t) * TILE_ELEMS;
#pragma unroll
            for (int it = 0; it < 2; it++) {
                int lin = tid + it * 256;
                int r = lin >> 2, q = lin & 3;      // 128 rows x 4 uint4
                *(uint4*)(tA + r * LDT + q * 8) =
                    *(const uint4*)(gA + (size_t)r * K + k0 + q * 8);
                *(uint4*)(tB + r * LDT + q * 8) =
                    *(const uint4*)(gB + (size_t)r * K + k0 + q * 8);
            }
        }
        __syncthreads();

#pragma unroll
        for (int tt = 0; tt < NTERMS; tt++) {
            uint32_t aBase = smbase + ta[tt] * TILE_ELEMS * 2;
            uint32_t bBase = smbase + (3 + tb[tt]) * TILE_ELEMS * 2;
#pragma unroll
            for (int ks = 0; ks < CH_K; ks += 16) {
                uint32_t a[2][4];
#pragma unroll
                for (int mt = 0; mt < 2; mt++) {
                    int R = wy * 32 + mt * 16;
                    uint32_t addr = aBase +
                        (uint32_t)(((R + a_row) * LDT) + ks + a_col) * 2;
                    LDSM_X4(a[mt][0], a[mt][1], a[mt][2], a[mt][3], addr);
                }
                uint32_t b[4][4];
#pragma unroll
                for (int np = 0; np < 4; np++) {
                    int Nb = wx * 64 + np * 16;
                    uint32_t addr = bBase +
                        (uint32_t)(((Nb + b_row) * LDT) + ks + b_col) * 2;
                    LDSM_X4(b[np][0], b[np][1], b[np][2], b[np][3], addr);
                }
#pragma unroll
                for (int mt = 0; mt < 2; mt++)
#pragma unroll
                    for (int np = 0; np < 4; np++) {
                        mma16816(acc[mt][np * 2 + 0], a[mt], b[np][0], b[np][1]);
                        mma16816(acc[mt][np * 2 + 1], a[mt], b[np][2], b[np][3]);
                    }
            }
        }

        // drain TC accumulator into fp32 master accumulator (IEEE RN adds)
#pragma unroll
        for (int mt = 0; mt < 2; mt++)
#pragma unroll
            for (int nt = 0; nt < 8; nt++)
#pragma unroll
                for (int e = 0; e < 4; e++) {
                    facc[mt][nt][e] += acc[mt][nt][e];
                    acc[mt][nt][e] = 0.f;
                }
    }

    // epilogue: c0,c1 -> (row, col..col+1); c2,c3 -> (row+8, ..)
#pragma unroll
    for (int mt = 0; mt < 2; mt++) {
        int row = row0 + wy * 32 + mt * 16 + (lane >> 2);
#pragma unroll
        for (int nt = 0; nt < 8; nt++) {
            int col = colbase + wx * 64 + nt * 8 + 2 * (lane & 3);
            float* p0 = C + (size_t)row * ldc + col;
            p0[0] = facc[mt][nt][0];
            p0[1] = facc[mt][nt][1];
            float* p1 = p0 + (size_t)8 * ldc;
            p1[0] = facc[mt][nt][2];
            p1[1] = facc[mt][nt][3];
        }
    }
}

// Fused QKV: grid (48,16); bx<32 Q, <40 K, else V — all 6-term
__global__ __launch_bounds__(256, 1) void qkv_mma(
    const __nv_bfloat16* x1, const __nv_bfloat16* x2, const __nv_bfloat16* x3,
    const __nv_bfloat16* wq1, const __nv_bfloat16* wq2, const __nv_bfloat16* wq3,
    const __nv_bfloat16* wk1, const __nv_bfloat16* wk2, const __nv_bfloat16* wk3,
    const __nv_bfloat16* wv1, const __nv_bfloat16* wv2, const __nv_bfloat16* wv3,
    float* Qo, float* Ko, float* Vo)
{
    int bx = blockIdx.x, by = blockIdx.y;
    int row0 = by * 128;
    size_t aoff = (size_t)row0 * HID;
    if (bx < 32) {
        size_t boff = (size_t)bx * 128 * HID;
        mma_gemm_body(x1 + aoff, x2 + aoff, x3 + aoff,
                      wq1 + boff, wq2 + boff, wq3 + boff,
                      Qo, HID, bx * 128, row0, HID);
    } else if (bx < 40) {
        int cb = bx - 32;
        size_t boff = (size_t)cb * 128 * HID;
        mma_gemm_body(x1 + aoff, x2 + aoff, x3 + aoff,
                      wk1 + boff, wk2 + boff, wk3 + boff,
                      Ko, KVDIM, cb * 128, row0, HID);
    } else {
        int cb = bx - 40;
        size_t boff = (size_t)cb * 128 * HID;
        mma_gemm_body(x1 + aoff, x2 + aoff, x3 + aoff,
                      wv1 + boff, wv2 + boff, wv3 + boff,
                      Vo, KVDIM, cb * 128, row0, HID);
    }
}

__global__ __launch_bounds__(256, 1) void o_mma(
    const __nv_bfloat16* a1, const __nv_bfloat16* a2, const __nv_bfloat16* a3,
    const __nv_bfloat16* w1, const __nv_bfloat16* w2, const __nv_bfloat16* w3,
    float* C)
{
    int bx = blockIdx.x, by = blockIdx.y;
    int row0 = by * 128;
    size_t aoff = (size_t)row0 * HID;
    size_t boff = (size_t)bx * 128 * HID;
    mma_gemm_body(a1 + aoff, a2 + aoff, a3 + aoff,
                  w1 + boff, w2 + boff, w3 + boff,
                  C, HID, bx * 128, row0, HID);
}

// ---------------- split fp32 -> bf16 hi/lo/lo2 ------------------------------
__global__ void split_kernel(const float* __restrict__ in,
                             __nv_bfloat16* __restrict__ o1,
                             __nv_bfloat16* __restrict__ o2,
                             __nv_bfloat16* __restrict__ o3,
                             int n)
{
    int i = blockIdx.x * blockDim.x + threadIdx.x;
    if (i >= n) return;
    float v = in[i];
    __nv_bfloat16 b1 = __float2bfloat16_rn(v);
    float r = v - __bfloat162float(b1);
    __nv_bfloat16 b2 = __float2bfloat16_rn(r);
    float r2 = r - __bfloat162float(b2);
    o1[i] = b1; o2[i] = b2;
    o3[i] = __float2bfloat16_rn(r2);
}

// ---------------- fake_quant_sparse: K (per-column, n=2048) -----------------
__global__ __launch_bounds__(256) void quant_k_cols(float* __restrict__ Kd)
{
    const int n = 2048;
    __shared__ float s[2048];
    __shared__ float red[256];
    int col = blockIdx.x;
    int tid = threadIdx.x;
    float vals[8];
#pragma unroll
    for (int i = 0; i < 8; i++) {
        float v = Kd[(size_t)(i * 256 + tid) * KVDIM + col];
        vals[i] = v;
        s[i * 256 + tid] = v;
    }
    __syncthreads();
    for (int k = 2; k <= n; k <<= 1) {
        for (int j = k >> 1; j > 0; j >>= 1) {
            for (int t = tid; t < n; t += 256) {
                int ixj = t ^ j;
                if (ixj > t) {
                    float a = s[t], b = s[ixj];
                    bool up = ((t & k) == 0);
                    if ((a > b) == up) { s[t] = b; s[ixj] = a; }
                }
            }
            __syncthreads();
        }
    }
    float tq = 1.0f - (1.0f - 0.999f) / 2.0f;
    float plo = (1.0f - tq) * (n - 1);
    float phi = tq * (n - 1);
    int ilo = (int)plo, ihi = (int)phi;
    float flo = plo - ilo, fhi = phi - ihi;
    float lower = s[ilo] + flo * (s[ilo + 1] - s[ilo]);
    float upper = s[ihi] + fhi * (s[ihi + 1] - s[ihi]);
    float med = s[(n - 1) / 2];
    float mn = FLT_MAX, mx = -FLT_MAX;
#pragma unroll
    for (int i = 0; i < 8; i++) {
        float x = vals[i];
        bool mask = (x <= lower) || (x >= upper);
        float tv = mask ? med : x;
        mn = fminf(mn, tv);
        mx = fmaxf(mx, tv);
    }
    red[tid] = mn; __syncthreads();
    for (int off = 128; off; off >>= 1) {
        if (tid < off) red[tid] = fminf(red[tid], red[tid + off]);
        __syncthreads();
    }
    mn = red[0]; __syncthreads();
    red[tid] = mx; __syncthreads();
    for (int off = 128; off; off >>= 1) {
        if (tid < off) red[tid] = fmaxf(red[tid], red[tid + off]);
        __syncthreads();
    }
    mx = red[0];
    float qx = 15.0f / (mx - mn);
    float offn = mn * qx;
#pragma unroll
    for (int i = 0; i < 8; i++) {
        float x = vals[i];
        bool mask = (x <= lower) || (x >= upper);
        float out;
        if (mask) out = x;
        else {
            float q = rintf(qx * x - offn);
            q = fminf(fmaxf(q, 0.f), 15.f);
            out = (q + offn) / qx;
        }
        if (!isfinite(out)) out = 0.f;
        Kd[(size_t)(i * 256 + tid) * KVDIM + col] = out;
    }
}

// ---------------- fake_quant_sparse: V (per-row, n=1024) --------------------
__global__ __launch_bounds__(256) void quant_v_rows(float* __restrict__ Vd)
{
    const int n = 1024;
    __shared__ float s[1024];
    __shared__ float red[256];
    int row = blockIdx.x;
    int tid = threadIdx.x;
    float* rp = Vd + (size_t)row * KVDIM;
    float vals[4];
#pragma unroll
    for (int i = 0; i < 4; i++) {
        float v = rp[i * 256 + tid];
        vals[i] = v;
        s[i * 256 + tid] = v;
    }
    __syncthreads();
    for (int k = 2; k <= n; k <<= 1) {
        for (int j = k >> 1; j > 0; j >>= 1) {
            for (int t = tid; t < n; t += 256) {
                int ixj = t ^ j;
                if (ixj > t) {
                    float a = s[t], b = s[ixj];
                    bool up = ((t & k) == 0);
                    if ((a > b) == up) { s[t] = b; s[ixj] = a; }
                }
            }
            __syncthreads();
        }
    }
    float tq = 1.0f - (1.0f - 0.999f) / 2.0f;
    float plo = (1.0f - tq) * (n - 1);
    float phi = tq * (n - 1);
    int ilo = (int)plo, ihi = (int)phi;
    float flo = plo - ilo, fhi = phi - ihi;
    float lower = s[ilo] + flo * (s[ilo + 1] - s[ilo]);
    float upper = s[ihi] + fhi * (s[ihi + 1] - s[ihi]);
    float med = s[(n - 1) / 2];
    float mn = FLT_MAX, mx = -FLT_MAX;
#pragma unroll
    for (int i = 0; i < 4; i++) {
        float x = vals[i];
        bool mask = (x <= lower) || (x >= upper);
        float tv = mask ? med : x;
        mn = fminf(mn, tv);
        mx = fmaxf(mx, tv);
    }
    red[tid] = mn; __syncthreads();
    for (int off = 128; off; off >>= 1) {
        if (tid < off) red[tid] = fminf(red[tid], red[tid + off]);
        __syncthreads();
    }
    mn = red[0]; __syncthreads();
    red[tid] = mx; __syncthreads();
    for (int off = 128; off; off >>= 1) {
        if (tid < off) red[tid] = fmaxf(red[tid], red[tid + off]);
        __syncthreads();
    }
    mx = red[0];
    float qx = 15.0f / (mx - mn);
    float offn = mn * qx;
#pragma unroll
    for (int i = 0; i < 4; i++) {
        float x = vals[i];
        bool mask = (x <= lower) || (x >= upper);
        float out;
        if (mask) out = x;
        else {
            float q = rintf(qx * x - offn);
            q = fminf(fmaxf(q, 0.f), 15.f);
            out = (q + offn) / qx;
        }
        if (!isfinite(out)) out = 0.f;
        rp[i * 256 + tid] = out;
    }
}

// ---------------- RoPE ------------------------------------------------------
__global__ void rope_kernel(float* __restrict__ X, int nheads)
{
    int idx = blockIdx.x * blockDim.x + threadIdx.x;
    int total = BATCH * SEQ * nheads * 64;
    if (idx >= total) return;
    int i = idx & 63;
    int rest = idx >> 6;
    int sh = rest / nheads;
    int spos = sh & (SEQ - 1);
    double expo = (double)(2 * i) / 128.0;
    float invf = (float)exp(-expo * 9.210340371976184);
    float f = (float)spos * invf;
    double fd = (double)f;
    double r = fd - rint(fd * 0.15915494309189535) * 6.283185307179586;
    float rf = (float)r;
    float c = cosf(rf), sn = sinf(rf);
    size_t base = (size_t)rest * 128 + i;
    float lo = X[base], hi = X[base + 64];
    X[base]      = lo * c - hi * sn;
    X[base + 64] = hi * c + lo * sn;
}

// ---------------- causal flash attention, fp32 ------------------------------
#define QST 68
#define ATTN_SMEM ((128*QST + 128*QST + 64*128 + 64*QST) * 4)

__global__ __launch_bounds__(256) void attn_kernel(const float* __restrict__ Q,
                                                   const float* __restrict__ Km,
                                                   const float* __restrict__ Vm,
                                                   float* __restrict__ O)
{
    extern __shared__ float smb[];
    float* Qst = smb;
    float* Kst = Qst + 128 * QST;
    float* Vs  = Kst + 128 * QST;
    float* Sst = Vs + 64 * 128;
    int qt = (SEQ / 64 - 1) - blockIdx.x;
    int h = blockIdx.y, b = blockIdx.z;
    int kvh = h >> 2;
    int tid = threadIdx.x;
    int tx = tid & 15, ty = tid >> 4;
    int q0 = qt * 64;

    for (int t = tid; t < 64 * 32; t += 256) {
        int rr = t >> 5, cc = (t & 31) << 2;
        float4 v = *(const float4*)&Q[(((size_t)(b * SEQ + q0 + rr)) * NH + h) * HD + cc];
        Qst[(cc + 0) * QST + rr] = v.x;
        Qst[(cc + 1) * QST + rr] = v.y;
        Qst[(cc + 2) * QST + rr] = v.z;
        Qst[(cc + 3) * QST + rr] = v.w;
    }

    float m_run[4], l_run[4], acc[4][8];
#pragma unroll
    for (int i = 0; i < 4; i++) {
        m_run[i] = -FLT_MAX; l_run[i] = 0.f;
#pragma unroll
        for (int j = 0; j < 8; j++) acc[i][j] = 0.f;
    }
    const float scale = 0.08838834764831845f;

    for (int jt = 0; jt <= qt; jt++) {
        int k0 = jt * 64;
        __syncthreads();
        for (int t = tid; t < 64 * 32; t += 256) {
            int rr = t >> 5, cc = (t & 31) << 2;
            size_t gi = (((size_t)(b * SEQ + k0 + rr)) * KVH + kvh) * HD + cc;
            float4 kv = *(const float4*)&Km[gi];
            Kst[(cc + 0) * QST + rr] = kv.x;
            Kst[(cc + 1) * QST + rr] = kv.y;
            Kst[(cc + 2) * QST + rr] = kv.z;
            Kst[(cc + 3) * QST + rr] = kv.w;
            *(float4*)&Vs[rr * 128 + cc] = *(const float4*)&Vm[gi];
        }
        __syncthreads();

        float s4[4][4];
#pragma unroll
        for (int i = 0; i < 4; i++)
#pragma unroll
            for (int j = 0; j < 4; j++) s4[i][j] = 0.f;
#pragma unroll 4
        for (int d = 0; d < 128; d++) {
            float4 qv = *(const float4*)&Qst[d * QST + ty * 4];
            float4 kv = *(const float4*)&Kst[d * QST + tx * 4];
            float qa[4] = {qv.x, qv.y, qv.z, qv.w};
            float ka[4] = {kv.x, kv.y, kv.z, kv.w};
#pragma unroll
            for (int i = 0; i < 4; i++)
#pragma unroll
                for (int j = 0; j < 4; j++)
                    s4[i][j] = fmaf(qa[i], ka[j], s4[i][j]);
        }
#pragma unroll
        for (int i = 0; i < 4; i++) {
            int qi = q0 + ty * 4 + i;
#pragma unroll
            for (int j = 0; j < 4; j++) {
                int kj = k0 + tx * 4 + j;
                float sv = s4[i][j] * scale;
                s4[i][j] = (kj > qi) ? -FLT_MAX : sv;
            }
        }
#pragma unroll
        for (int i = 0; i < 4; i++) {
            float mloc = fmaxf(fmaxf(s4[i][0], s4[i][1]), fmaxf(s4[i][2], s4[i][3]));
            mloc = fmaxf(mloc, __shfl_xor_sync(0xffffffffu, mloc, 8, 16));
            mloc = fmaxf(mloc, __shfl_xor_sync(0xffffffffu, mloc, 4, 16));
            mloc = fmaxf(mloc, __shfl_xor_sync(0xffffffffu, mloc, 2, 16));
            mloc = fmaxf(mloc, __shfl_xor_sync(0xffffffffu, mloc, 1, 16));
            float mn = fmaxf(m_run[i], mloc);
            float corr = expf(m_run[i] - mn);
            m_run[i] = mn;
            float sloc = 0.f;
#pragma unroll
            for (int j = 0; j < 4; j++) {
                float p = expf(s4[i][j] - mn);
                s4[i][j] = p;
                sloc += p;
            }
            sloc += __shfl_xor_sync(0xffffffffu, sloc, 8, 16);
            sloc += __shfl_xor_sync(0xffffffffu, sloc, 4, 16);
            sloc += __shfl_xor_sync(0xffffffffu, sloc, 2, 16);
            sloc += __shfl_xor_sync(0xffffffffu, sloc, 1, 16);
            l_run[i] = l_run[i] * corr + sloc;
#pragma unroll
            for (int j = 0; j < 8; j++) acc[i][j] *= corr;
        }
#pragma unroll
        for (int i = 0; i < 4; i++)
#pragma unroll
            for (int j = 0; j < 4; j++)
                Sst[(tx * 4 + j) * QST + (ty * 4 + i)] = s4[i][j];
        __syncthreads();
#pragma unroll 2
        for (int c = 0; c < 64; c++) {
            float4 pv = *(const float4*)&Sst[c * QST + ty * 4];
            float4 v0 = *(const float4*)&Vs[c * 128 + tx * 8];
            float4 v1 = *(const float4*)&Vs[c * 128 + tx * 8 + 4];
            float p[4] = {pv.x, pv.y, pv.z, pv.w};
            float vv[8] = {v0.x, v0.y, v0.z, v0.w, v1.x, v1.y, v1.z, v1.w};
#pragma unroll
            for (int i = 0; i < 4; i++)
#pragma unroll
                for (int j = 0; j < 8; j++)
                    acc[i][j] = fmaf(p[i], vv[j], acc[i][j]);
        }
    }
#pragma unroll
    for (int i = 0; i < 4; i++) {
        float inv = 1.0f / l_run[i];
        int row = q0 + ty * 4 + i;
        float* op = O + (((size_t)(b * SEQ + row)) * NH + h) * HD + tx * 8;
        *(float4*)op       = make_float4(acc[i][0] * inv, acc[i][1] * inv, acc[i][2] * inv, acc[i][3] * inv);
        *(float4*)(op + 4) = make_float4(acc[i][4] * inv, acc[i][5] * inv, acc[i][6] * inv, acc[i][7] * inv);
    }
}

// ---------------- launch ----------------------------------------------------
extern "C" void kernel_launch(void* const* d_in, const int* in_sizes, int n_in,
                              void* d_out, int out_size)
{
    (void)in_sizes; (void)n_in; (void)out_size;
    const float* X  = (const float*)d_in[0];
    const float* Wq = (const float*)d_in[1];
    const float* Wk = (const float*)d_in[2];
    const float* Wv = (const float*)d_in[3];
    const float* Wo = (const float*)d_in[4];
    float* out = (float*)d_out;

    void *pQ, *pK, *pV, *pA;
    cudaGetSymbolAddress(&pQ, g_Q);
    cudaGetSymbolAddress(&pK, g_K);
    cudaGetSymbolAddress(&pV, g_V);
    cudaGetSymbolAddress(&pA, g_A);
    void *px1, *px2, *px3, *pq1, *pq2, *pq3, *pk1, *pk2, *pk3;
    void *pv1, *pv2, *pv3, *pa1, *pa2, *pa3, *po1, *po2, *po3;
    cudaGetSymbolAddress(&px1, sX1); cudaGetSymbolAddress(&px2, sX2);
    cudaGetSymbolAddress(&px3, sX3);
    cudaGetSymbolAddress(&pq1, sWq1); cudaGetSymbolAddress(&pq2, sWq2);
    cudaGetSymbolAddress(&pq3, sWq3);
    cudaGetSymbolAddress(&pk1, sWk1); cudaGetSymbolAddress(&pk2, sWk2);
    cudaGetSymbolAddress(&pk3, sWk3);
    cudaGetSymbolAddress(&pv1, sWv1); cudaGetSymbolAddress(&pv2, sWv2);
    cudaGetSymbolAddress(&pv3, sWv3);
    cudaGetSymbolAddress(&pa1, sA1);  cudaGetSymbolAddress(&pa2, sA2);
    cudaGetSymbolAddress(&pa3, sA3);
    cudaGetSymbolAddress(&po1, sWo1); cudaGetSymbolAddress(&po2, sWo2);
    cudaGetSymbolAddress(&po3, sWo3);

    cudaFuncSetAttribute(attn_kernel, cudaFuncAttributeMaxDynamicSharedMemorySize, ATTN_SMEM);
    cudaFuncSetAttribute(qkv_mma, cudaFuncAttributeMaxDynamicSharedMemorySize, MMA_SMEM);
    cudaFuncSetAttribute(o_mma,   cudaFuncAttributeMaxDynamicSharedMemorySize, MMA_SMEM);

    // splits: all 3-way
    int nX = ROWS * HID, nWq = HID * HID, nWkv = KVDIM * HID;
    split_kernel<<<(nX + 255) / 256, 256>>>(X, (__nv_bfloat16*)px1, (__nv_bfloat16*)px2,
                                            (__nv_bfloat16*)px3, nX);
    split_kernel<<<(nWq + 255) / 256, 256>>>(Wq, (__nv_bfloat16*)pq1, (__nv_bfloat16*)pq2,
                                             (__nv_bfloat16*)pq3, nWq);
    split_kernel<<<(nWkv + 255) / 256, 256>>>(Wk, (__nv_bfloat16*)pk1, (__nv_bfloat16*)pk2,
                                              (__nv_bfloat16*)pk3, nWkv);
    split_kernel<<<(nWkv + 255) / 256, 256>>>(Wv, (__nv_bfloat16*)pv1, (__nv_bfloat16*)pv2,
                                              (__nv_bfloat16*)pv3, nWkv);
    split_kernel<<<(nWq + 255) / 256, 256>>>(Wo, (__nv_bfloat16*)po1, (__nv_bfloat16*)po2,
                                             (__nv_bfloat16*)po3, nWq);

    qkv_mma<<<dim3(48, 16), 256, MMA_SMEM>>>(
        (const __nv_bfloat16*)px1, (const __nv_bfloat16*)px2, (const __nv_bfloat16*)px3,
        (const __nv_bfloat16*)pq1, (const __nv_bfloat16*)pq2, (const __nv_bfloat16*)pq3,
        (const __nv_bfloat16*)pk1, (const __nv_bfloat16*)pk2, (const __nv_bfloat16*)pk3,
        (const __nv_bfloat16*)pv1, (const __nv_bfloat16*)pv2, (const __nv_bfloat16*)pv3,
        (float*)pQ, (float*)pK, (float*)pV);

    quant_k_cols<<<KVDIM, 256>>>((float*)pK);
    quant_v_rows<<<ROWS, 256>>>((float*)pV);

    rope_kernel<<<(BATCH * SEQ * NH * 64 + 255) / 256, 256>>>((float*)pQ, NH);
    rope_kernel<<<(BATCH * SEQ * KVH * 64 + 255) / 256, 256>>>((float*)pK, KVH);

    attn_kernel<<<dim3(SEQ / 64, NH, BATCH), 256, ATTN_SMEM>>>(
        (const float*)pQ, (const float*)pK, (const float*)pV, (float*)pA);

    split_kernel<<<(nX + 255) / 256, 256>>>((const float*)pA, (__nv_bfloat16*)pa1,
                                            (__nv_bfloat16*)pa2, (__nv_bfloat16*)pa3, nX);
    o_mma<<<dim3(32, 16), 256, MMA_SMEM>>>(
        (const __nv_bfloat16*)pa1, (const __nv_bfloat16*)pa2, (const __nv_bfloat16*)pa3,
        (const __nv_bfloat16*)po1, (const __nv_bfloat16*)po2, (const __nv_bfloat16*)po3,
        out);
}

// round 14
// speedup vs baseline: 1.3659x; 1.3033x over previous
#include <cuda_runtime.h>
#include <cuda_bf16.h>
#include <cfloat>
#include <math.h>
#include <stdint.h>

// Problem constants
#define BATCH 2
#define SEQ 1024
#define HID 4096
#define NH 32
#define KVH 8
#define HD 128
#define ROWS (BATCH*SEQ)          // 2048
#define KVDIM (KVH*HD)            // 1024

// ---------------- scratch (static __device__, no allocation) ----------------
__device__ float g_Q[ROWS * HID];     // (b,s,32,128)
__device__ float g_K[ROWS * KVDIM];
__device__ float g_V[ROWS * KVDIM];
__device__ float g_A[ROWS * HID];     // attention output

// bf16 split operands
__device__ __nv_bfloat16 sX1[ROWS * HID], sX2[ROWS * HID], sX3[ROWS * HID];
__device__ __nv_bfloat16 sWq1[HID * HID], sWq2[HID * HID], sWq3[HID * HID];
__device__ __nv_bfloat16 sWk1[KVDIM * HID], sWk2[KVDIM * HID], sWk3[KVDIM * HID];
__device__ __nv_bfloat16 sWv1[KVDIM * HID], sWv2[KVDIM * HID], sWv3[KVDIM * HID];
__device__ __nv_bfloat16 sA1[ROWS * HID], sA2[ROWS * HID], sA3[ROWS * HID];
__device__ __nv_bfloat16 sWo1[HID * HID], sWo2[HID * HID], sWo3[HID * HID];

// ---------------- mma.sync helpers (baseline PTX, sm_80+) -------------------
__device__ __forceinline__ uint32_t smem_u32(const void* p) {
    uint32_t a;
    asm("{ .reg .u64 t; cvta.to.shared.u64 t, %1; cvt.u32.u64 %0, t; }"
        : "=r"(a) : "l"(p));
    return a;
}

#define LDSM_X4(r0, r1, r2, r3, addr) \
    asm volatile("ldmatrix.sync.aligned.m8n8.x4.shared.b16 {%0,%1,%2,%3}, [%4];" \
                 : "=r"(r0), "=r"(r1), "=r"(r2), "=r"(r3) : "r"(addr))

__device__ __forceinline__ void mma16816(float* c, const uint32_t* a,
                                         uint32_t b0, uint32_t b1)
{
    asm volatile(
        "mma.sync.aligned.m16n8k16.row.col.f32.bf16.bf16.f32 "
        "{%0,%1,%2,%3}, {%4,%5,%6,%7}, {%8,%9}, {%0,%1,%2,%3};"
        : "+f"(c[0]), "+f"(c[1]), "+f"(c[2]), "+f"(c[3])
        : "r"(a[0]), "r"(a[1]), "r"(a[2]), "r"(a[3]), "r"(b0), "r"(b1));
}

// ---------------- split-bf16 GEMM via mma.sync: C[128,128] = A * B^T --------
// terms==3: a1b1 + a1b2 + a2b1            (error ~1e-5, smooth paths only)
// terms==6: + a2b2 + a1b3 + a3b1          (exact to 2^-27, for K/V)
// TC accumulation is non-IEEE (R12/R13 experiment): drain into fp32 master
// accumulator with IEEE RN adds after EVERY K-chunk (TC chain <= 12 steps).
#define LDT 40                        // smem tile stride in bf16 (80B, 16B-mult)
#define CH_K 32                       // k per chunk
#define TILE_ELEMS (128 * LDT)        // per tile slot, bf16
#define MMA_SMEM (6 * TILE_ELEMS * 2) // 61440 bytes

__device__ __forceinline__ void mma_gemm_body(
    const __nv_bfloat16* A1, const __nv_bfloat16* A2, const __nv_bfloat16* A3,
    const __nv_bfloat16* B1, const __nv_bfloat16* B2, const __nv_bfloat16* B3,
    float* C, int ldc, int colbase, int row0, int K, int terms)
{
    extern __shared__ __nv_bfloat16 sm[];
    uint32_t smbase = smem_u32(sm);
    int tid = threadIdx.x;
    int wid = tid >> 5, lane = tid & 31;
    int wy = wid >> 1, wx = wid & 1;          // warp tile: rows wy*32, cols wx*64
    int nAB = (terms == 6) ? 3 : 2;
    const __nv_bfloat16* Ap[3] = {A1, A2, A3};
    const __nv_bfloat16* Bp[3] = {B1, B2, B3};
    const int ta[6] = {0, 0, 1, 1, 0, 2};
    const int tb[6] = {0, 1, 0, 1, 2, 0};

    float acc[2][8][4];    // TC accumulator (short chains only)
    float facc[2][8][4];   // fp32 master accumulator (IEEE RN adds)
#pragma unroll
    for (int mt = 0; mt < 2; mt++)
#pragma unroll
        for (int nt = 0; nt < 8; nt++)
#pragma unroll
            for (int e = 0; e < 4; e++) { acc[mt][nt][e] = 0.f; facc[mt][nt][e] = 0.f; }

    // per-lane ldmatrix address components (element units within a tile)
    int a_row = ((lane >> 3) & 1) * 8 + (lane & 7);  // + R
    int a_col = (lane >> 4) * 8;                      // + ks
    int b_row = (lane >> 4) * 8 + (lane & 7);         // + Nb
    int b_col = ((lane >> 3) & 1) * 8;                // + ks

    int nchunks = K / CH_K;
    for (int ch = 0; ch < nchunks; ch++) {
        int k0 = ch * CH_K;
        __syncthreads();                      // previous chunk's compute done
#pragma unroll
        for (int t = 0; t < 3; t++) {
            if (t >= nAB) break;
            const __nv_bfloat16* gA = Ap[t];
            const __nv_bfloat16* gB = Bp[t];
            __nv_bfloat16* tA = sm + t * TILE_ELEMS;
            __nv_bfloat16* tB = sm + (3 + t) * TILE_ELEMS;
#pragma unroll
            for (int it = 0; it < 2; it++) {
                int lin = tid + it * 256;
                int r = lin >> 2, q = lin & 3;      // 128 rows x 4 uint4
                *(uint4*)(tA + r * LDT + q * 8) =
                    *(const uint4*)(gA + (size_t)r * K + k0 + q * 8);
                *(uint4*)(tB + r * LDT + q * 8) =
                    *(const uint4*)(gB + (size_t)r * K + k0 + q * 8);
            }
        }
        __syncthreads();

        for (int tt = 0; tt < terms; tt++) {
            uint32_t aBase = smbase + ta[tt] * TILE_ELEMS * 2;
            uint32_t bBase = smbase + (3 + tb[tt]) * TILE_ELEMS * 2;
#pragma unroll
            for (int ks = 0; ks < CH_K; ks += 16) {
                uint32_t a[2][4];
#pragma unroll
                for (int mt = 0; mt < 2; mt++) {
                    int R = wy * 32 + mt * 16;
                    uint32_t addr = aBase +
                        (uint32_t)(((R + a_row) * LDT) + ks + a_col) * 2;
                    LDSM_X4(a[mt][0], a[mt][1], a[mt][2], a[mt][3], addr);
                }
                uint32_t b[4][4];
#pragma unroll
                for (int np = 0; np < 4; np++) {
                    int Nb = wx * 64 + np * 16;
                    uint32_t addr = bBase +
                        (uint32_t)(((Nb + b_row) * LDT) + ks + b_col) * 2;
                    LDSM_X4(b[np][0], b[np][1], b[np][2], b[np][3], addr);
                }
#pragma unroll
                for (int mt = 0; mt < 2; mt++)
#pragma unroll
                    for (int np = 0; np < 4; np++) {
                        mma16816(acc[mt][np * 2 + 0], a[mt], b[np][0], b[np][1]);
                        mma16816(acc[mt][np * 2 + 1], a[mt], b[np][2], b[np][3]);
                    }
            }
        }

        // drain TC accumulator into fp32 master accumulator (IEEE RN adds)
#pragma unroll
        for (int mt = 0; mt < 2; mt++)
#pragma unroll
            for (int nt = 0; nt < 8; nt++)
#pragma unroll
                for (int e = 0; e < 4; e++) {
                    facc[mt][nt][e] += acc[mt][nt][e];
                    acc[mt][nt][e] = 0.f;
                }
    }

    // epilogue: c0,c1 -> (row, col..col+1); c2,c3 -> (row+8, ..)
#pragma unroll
    for (int mt = 0; mt < 2; mt++) {
        int row = row0 + wy * 32 + mt * 16 + (lane >> 2);
#pragma unroll
        for (int nt = 0; nt < 8; nt++) {
            int col = colbase + wx * 64 + nt * 8 + 2 * (lane & 3);
            float* p0 = C + (size_t)row * ldc + col;
            p0[0] = facc[mt][nt][0];
            p0[1] = facc[mt][nt][1];
            float* p1 = p0 + (size_t)8 * ldc;
            p1[0] = facc[mt][nt][2];
            p1[1] = facc[mt][nt][3];
        }
    }
}

// Fused QKV: grid (48,16); bx<32 Q (3 terms), <40 K (6), else V (6)
__global__ __launch_bounds__(256, 1) void qkv_mma(
    const __nv_bfloat16* x1, const __nv_bfloat16* x2, const __nv_bfloat16* x3,
    const __nv_bfloat16* wq1, const __nv_bfloat16* wq2, const __nv_bfloat16* wq3,
    const __nv_bfloat16* wk1, const __nv_bfloat16* wk2, const __nv_bfloat16* wk3,
    const __nv_bfloat16* wv1, const __nv_bfloat16* wv2, const __nv_bfloat16* wv3,
    float* Qo, float* Ko, float* Vo)
{
    int bx = blockIdx.x, by = blockIdx.y;
    int row0 = by * 128;
    size_t aoff = (size_t)row0 * HID;
    if (bx < 32) {
        size_t boff = (size_t)bx * 128 * HID;
        mma_gemm_body(x1 + aoff, x2 + aoff, x3 + aoff,
                      wq1 + boff, wq2 + boff, wq3 + boff,
                      Qo, HID, bx * 128, row0, HID, 3);
    } else if (bx < 40) {
        int cb = bx - 32;
        size_t boff = (size_t)cb * 128 * HID;
        mma_gemm_body(x1 + aoff, x2 + aoff, x3 + aoff,
                      wk1 + boff, wk2 + boff, wk3 + boff,
                      Ko, KVDIM, cb * 128, row0, HID, 6);
    } else {
        int cb = bx - 40;
        size_t boff = (size_t)cb * 128 * HID;
        mma_gemm_body(x1 + aoff, x2 + aoff, x3 + aoff,
                      wv1 + boff, wv2 + boff, wv3 + boff,
                      Vo, KVDIM, cb * 128, row0, HID, 6);
    }
}

__global__ __launch_bounds__(256, 1) void o_mma(
    const __nv_bfloat16* a1, const __nv_bfloat16* a2, const __nv_bfloat16* a3,
    const __nv_bfloat16* w1, const __nv_bfloat16* w2, const __nv_bfloat16* w3,
    float* C)
{
    int bx = blockIdx.x, by = blockIdx.y;
    int row0 = by * 128;
    size_t aoff = (size_t)row0 * HID;
    size_t boff = (size_t)bx * 128 * HID;
    mma_gemm_body(a1 + aoff, a2 + aoff, a3 + aoff,
                  w1 + boff, w2 + boff, w3 + boff,
                  C, HID, bx * 128, row0, HID, 3);
}

// ---------------- split fp32 -> bf16 hi/lo/lo2 ------------------------------
__global__ void split_kernel(const float* __restrict__ in,
                             __nv_bfloat16* __restrict__ o1,
                             __nv_bfloat16* __restrict__ o2,
                             __nv_bfloat16* __restrict__ o3,
                             int n)
{
    int i = blockIdx.x * blockDim.x + threadIdx.x;
    if (i >= n) return;
    float v = in[i];
    __nv_bfloat16 b1 = __float2bfloat16_rn(v);
    float r = v - __bfloat162float(b1);
    __nv_bfloat16 b2 = __float2bfloat16_rn(r);
    float r2 = r - __bfloat162float(b2);
    o1[i] = b1; o2[i] = b2;
    o3[i] = __float2bfloat16_rn(r2);
}

// ---------------- fake_quant_sparse: K (per-column, n=2048) -----------------
__global__ __launch_bounds__(256) void quant_k_cols(float* __restrict__ Kd)
{
    const int n = 2048;
    __shared__ float s[2048];
    __shared__ float red[256];
    int col = blockIdx.x;
    int tid = threadIdx.x;
    float vals[8];
#pragma unroll
    for (int i = 0; i < 8; i++) {
        float v = Kd[(size_t)(i * 256 + tid) * KVDIM + col];
        vals[i] = v;
        s[i * 256 + tid] = v;
    }
    __syncthreads();
    for (int k = 2; k <= n; k <<= 1) {
        for (int j = k >> 1; j > 0; j >>= 1) {
            for (int t = tid; t < n; t += 256) {
                int ixj = t ^ j;
                if (ixj > t) {
                    float a = s[t], b = s[ixj];
                    bool up = ((t & k) == 0);
                    if ((a > b) == up) { s[t] = b; s[ixj] = a; }
                }
            }
            __syncthreads();
        }
    }
    float tq = 1.0f - (1.0f - 0.999f) / 2.0f;
    float plo = (1.0f - tq) * (n - 1);
    float phi = tq * (n - 1);
    int ilo = (int)plo, ihi = (int)phi;
    float flo = plo - ilo, fhi = phi - ihi;
    float lower = s[ilo] + flo * (s[ilo + 1] - s[ilo]);
    float upper = s[ihi] + fhi * (s[ihi + 1] - s[ihi]);
    float med = s[(n - 1) / 2];
    float mn = FLT_MAX, mx = -FLT_MAX;
#pragma unroll
    for (int i = 0; i < 8; i++) {
        float x = vals[i];
        bool mask = (x <= lower) || (x >= upper);
        float tv = mask ? med : x;
        mn = fminf(mn, tv);
        mx = fmaxf(mx, tv);
    }
    red[tid] = mn; __syncthreads();
    for (int off = 128; off; off >>= 1) {
        if (tid < off) red[tid] = fminf(red[tid], red[tid + off]);
        __syncthreads();
    }
    mn = red[0]; __syncthreads();
    red[tid] = mx; __syncthreads();
    for (int off = 128; off; off >>= 1) {
        if (tid < off) red[tid] = fmaxf(red[tid], red[tid + off]);
        __syncthreads();
    }
    mx = red[0];
    float qx = 15.0f / (mx - mn);
    float offn = mn * qx;
#pragma unroll
    for (int i = 0; i < 8; i++) {
        float x = vals[i];
        bool mask = (x <= lower) || (x >= upper);
        float out;
        if (mask) out = x;
        else {
            float q = rintf(qx * x - offn);
            q = fminf(fmaxf(q, 0.f), 15.f);
            out = (q + offn) / qx;
        }
        if (!isfinite(out)) out = 0.f;
        Kd[(size_t)(i * 256 + tid) * KVDIM + col] = out;
    }
}

// ---------------- fake_quant_sparse: V (per-row, n=1024) --------------------
__global__ __launch_bounds__(256) void quant_v_rows(float* __restrict__ Vd)
{
    const int n = 1024;
    __shared__ float s[1024];
    __shared__ float red[256];
    int row = blockIdx.x;
    int tid = threadIdx.x;
    float* rp = Vd + (size_t)row * KVDIM;
    float vals[4];
#pragma unroll
    for (int i = 0; i < 4; i++) {
        float v = rp[i * 256 + tid];
        vals[i] = v;
        s[i * 256 + tid] = v;
    }
    __syncthreads();
    for (int k = 2; k <= n; k <<= 1) {
        for (int j = k >> 1; j > 0; j >>= 1) {
            for (int t = tid; t < n; t += 256) {
                int ixj = t ^ j;
                if (ixj > t) {
                    float a = s[t], b = s[ixj];
                    bool up = ((t & k) == 0);
                    if ((a > b) == up) { s[t] = b; s[ixj] = a; }
                }
            }
            __syncthreads();
        }
    }
    float tq = 1.0f - (1.0f - 0.999f) / 2.0f;
    float plo = (1.0f - tq) * (n - 1);
    float phi = tq * (n - 1);
    int ilo = (int)plo, ihi = (int)phi;
    float flo = plo - ilo, fhi = phi - ihi;
    float lower = s[ilo] + flo * (s[ilo + 1] - s[ilo]);
    float upper = s[ihi] + fhi * (s[ihi + 1] - s[ihi]);
    float med = s[(n - 1) / 2];
    float mn = FLT_MAX, mx = -FLT_MAX;
#pragma unroll
    for (int i = 0; i < 4; i++) {
        float x = vals[i];
        bool mask = (x <= lower) || (x >= upper);
        float tv = mask ? med : x;
        mn = fminf(mn, tv);
        mx = fmaxf(mx, tv);
    }
    red[tid] = mn; __syncthreads();
    for (int off = 128; off; off >>= 1) {
        if (tid < off) red[tid] = fminf(red[tid], red[tid + off]);
        __syncthreads();
    }
    mn = red[0]; __syncthreads();
    red[tid] = mx; __syncthreads();
    for (int off = 128; off; off >>= 1) {
        if (tid < off) red[tid] = fmaxf(red[tid], red[tid + off]);
        __syncthreads();
    }
    mx = red[0];
    float qx = 15.0f / (mx - mn);
    float offn = mn * qx;
#pragma unroll
    for (int i = 0; i < 4; i++) {
        float x = vals[i];
        bool mask = (x <= lower) || (x >= upper);
        float out;
        if (mask) out = x;
        else {
            float q = rintf(qx * x - offn);
            q = fminf(fmaxf(q, 0.f), 15.f);
            out = (q + offn) / qx;
        }
        if (!isfinite(out)) out = 0.f;
        rp[i * 256 + tid] = out;
    }
}

// ---------------- RoPE ------------------------------------------------------
__global__ void rope_kernel(float* __restrict__ X, int nheads)
{
    int idx = blockIdx.x * blockDim.x + threadIdx.x;
    int total = BATCH * SEQ * nheads * 64;
    if (idx >= total) return;
    int i = idx & 63;
    int rest = idx >> 6;
    int sh = rest / nheads;
    int spos = sh & (SEQ - 1);
    double expo = (double)(2 * i) / 128.0;
    float invf = (float)exp(-expo * 9.210340371976184);
    float f = (float)spos * invf;
    double fd = (double)f;
    double r = fd - rint(fd * 0.15915494309189535) * 6.283185307179586;
    float rf = (float)r;
    float c = cosf(rf), sn = sinf(rf);
    size_t base = (size_t)rest * 128 + i;
    float lo = X[base], hi = X[base + 64];
    X[base]      = lo * c - hi * sn;
    X[base + 64] = hi * c + lo * sn;
}

// ---------------- causal flash attention, fp32 ------------------------------
#define QST 68
#define ATTN_SMEM ((128*QST + 128*QST + 64*128 + 64*QST) * 4)

__global__ __launch_bounds__(256) void attn_kernel(const float* __restrict__ Q,
                                                   const float* __restrict__ Km,
                                                   const float* __restrict__ Vm,
                                                   float* __restrict__ O)
{
    extern __shared__ float smb[];
    float* Qst = smb;
    float* Kst = Qst + 128 * QST;
    float* Vs  = Kst + 128 * QST;
    float* Sst = Vs + 64 * 128;
    int qt = (SEQ / 64 - 1) - blockIdx.x;
    int h = blockIdx.y, b = blockIdx.z;
    int kvh = h >> 2;
    int tid = threadIdx.x;
    int tx = tid & 15, ty = tid >> 4;
    int q0 = qt * 64;

    for (int t = tid; t < 64 * 32; t += 256) {
        int rr = t >> 5, cc = (t & 31) << 2;
        float4 v = *(const float4*)&Q[(((size_t)(b * SEQ + q0 + rr)) * NH + h) * HD + cc];
        Qst[(cc + 0) * QST + rr] = v.x;
        Qst[(cc + 1) * QST + rr] = v.y;
        Qst[(cc + 2) * QST + rr] = v.z;
        Qst[(cc + 3) * QST + rr] = v.w;
    }

    float m_run[4], l_run[4], acc[4][8];
#pragma unroll
    for (int i = 0; i < 4; i++) {
        m_run[i] = -FLT_MAX; l_run[i] = 0.f;
#pragma unroll
        for (int j = 0; j < 8; j++) acc[i][j] = 0.f;
    }
    const float scale = 0.08838834764831845f;

    for (int jt = 0; jt <= qt; jt++) {
        int k0 = jt * 64;
        __syncthreads();
        for (int t = tid; t < 64 * 32; t += 256) {
            int rr = t >> 5, cc = (t & 31) << 2;
            size_t gi = (((size_t)(b * SEQ + k0 + rr)) * KVH + kvh) * HD + cc;
            float4 kv = *(const float4*)&Km[gi];
            Kst[(cc + 0) * QST + rr] = kv.x;
            Kst[(cc + 1) * QST + rr] = kv.y;
            Kst[(cc + 2) * QST + rr] = kv.z;
            Kst[(cc + 3) * QST + rr] = kv.w;
            *(float4*)&Vs[rr * 128 + cc] = *(const float4*)&Vm[gi];
        }
        __syncthreads();

        float s4[4][4];
#pragma unroll
        for (int i = 0; i < 4; i++)
#pragma unroll
            for (int j = 0; j < 4; j++) s4[i][j] = 0.f;
#pragma unroll 4
        for (int d = 0; d < 128; d++) {
            float4 qv = *(const float4*)&Qst[d * QST + ty * 4];
            float4 kv = *(const float4*)&Kst[d * QST + tx * 4];
            float qa[4] = {qv.x, qv.y, qv.z, qv.w};
            float ka[4] = {kv.x, kv.y, kv.z, kv.w};
#pragma unroll
            for (int i = 0; i < 4; i++)
#pragma unroll
                for (int j = 0; j < 4; j++)
                    s4[i][j] = fmaf(qa[i], ka[j], s4[i][j]);
        }
#pragma unroll
        for (int i = 0; i < 4; i++) {
            int qi = q0 + ty * 4 + i;
#pragma unroll
            for (int j = 0; j < 4; j++) {
                int kj = k0 + tx * 4 + j;
                float sv = s4[i][j] * scale;
                s4[i][j] = (kj > qi) ? -FLT_MAX : sv;
            }
        }
#pragma unroll
        for (int i = 0; i < 4; i++) {
            float mloc = fmaxf(fmaxf(s4[i][0], s4[i][1]), fmaxf(s4[i][2], s4[i][3]));
            mloc = fmaxf(mloc, __shfl_xor_sync(0xffffffffu, mloc, 8, 16));
            mloc = fmaxf(mloc, __shfl_xor_sync(0xffffffffu, mloc, 4, 16));
            mloc = fmaxf(mloc, __shfl_xor_sync(0xffffffffu, mloc, 2, 16));
            mloc = fmaxf(mloc, __shfl_xor_sync(0xffffffffu, mloc, 1, 16));
            float mn = fmaxf(m_run[i], mloc);
            float corr = expf(m_run[i] - mn);
            m_run[i] = mn;
            float sloc = 0.f;
#pragma unroll
            for (int j = 0; j < 4; j++) {
                float p = expf(s4[i][j] - mn);
                s4[i][j] = p;
                sloc += p;
            }
            sloc += __shfl_xor_sync(0xffffffffu, sloc, 8, 16);
            sloc += __shfl_xor_sync(0xffffffffu, sloc, 4, 16);
            sloc += __shfl_xor_sync(0xffffffffu, sloc, 2, 16);
            sloc += __shfl_xor_sync(0xffffffffu, sloc, 1, 16);
            l_run[i] = l_run[i] * corr + sloc;
#pragma unroll
            for (int j = 0; j < 8; j++) acc[i][j] *= corr;
        }
#pragma unroll
        for (int i = 0; i < 4; i++)
#pragma unroll
            for (int j = 0; j < 4; j++)
                Sst[(tx * 4 + j) * QST + (ty * 4 + i)] = s4[i][j];
        __syncthreads();
#pragma unroll 2
        for (int c = 0; c < 64; c++) {
            float4 pv = *(const float4*)&Sst[c * QST + ty * 4];
            float4 v0 = *(const float4*)&Vs[c * 128 + tx * 8];
            float4 v1 = *(const float4*)&Vs[c * 128 + tx * 8 + 4];
            float p[4] = {pv.x, pv.y, pv.z, pv.w};
            float vv[8] = {v0.x, v0.y, v0.z, v0.w, v1.x, v1.y, v1.z, v1.w};
#pragma unroll
            for (int i = 0; i < 4; i++)
#pragma unroll
                for (int j = 0; j < 8; j++)
                    acc[i][j] = fmaf(p[i], vv[j], acc[i][j]);
        }
    }
#pragma unroll
    for (int i = 0; i < 4; i++) {
        float inv = 1.0f / l_run[i];
        int row = q0 + ty * 4 + i;
        float* op = O + (((size_t)(b * SEQ + row)) * NH + h) * HD + tx * 8;
        *(float4*)op       = make_float4(acc[i][0] * inv, acc[i][1] * inv, acc[i][2] * inv, acc[i][3] * inv);
        *(float4*)(op + 4) = make_float4(acc[i][4] * inv, acc[i][5] * inv, acc[i][6] * inv, acc[i][7] * inv);
    }
}

// ---------------- launch ----------------------------------------------------
extern "C" void kernel_launch(void* const* d_in, const int* in_sizes, int n_in,
                              void* d_out, int out_size)
{
    (void)in_sizes; (void)n_in; (void)out_size;
    const float* X  = (const float*)d_in[0];
    const float* Wq = (const float*)d_in[1];
    const float* Wk = (const float*)d_in[2];
    const float* Wv = (const float*)d_in[3];
    const float* Wo = (const float*)d_in[4];
    float* out = (float*)d_out;

    void *pQ, *pK, *pV, *pA;
    cudaGetSymbolAddress(&pQ, g_Q);
    cudaGetSymbolAddress(&pK, g_K);
    cudaGetSymbolAddress(&pV, g_V);
    cudaGetSymbolAddress(&pA, g_A);
    void *px1, *px2, *px3, *pq1, *pq2, *pq3, *pk1, *pk2, *pk3;
    void *pv1, *pv2, *pv3, *pa1, *pa2, *pa3, *po1, *po2, *po3;
    cudaGetSymbolAddress(&px1, sX1); cudaGetSymbolAddress(&px2, sX2);
    cudaGetSymbolAddress(&px3, sX3);
    cudaGetSymbolAddress(&pq1, sWq1); cudaGetSymbolAddress(&pq2, sWq2);
    cudaGetSymbolAddress(&pq3, sWq3);
    cudaGetSymbolAddress(&pk1, sWk1); cudaGetSymbolAddress(&pk2, sWk2);
    cudaGetSymbolAddress(&pk3, sWk3);
    cudaGetSymbolAddress(&pv1, sWv1); cudaGetSymbolAddress(&pv2, sWv2);
    cudaGetSymbolAddress(&pv3, sWv3);
    cudaGetSymbolAddress(&pa1, sA1);  cudaGetSymbolAddress(&pa2, sA2);
    cudaGetSymbolAddress(&pa3, sA3);
    cudaGetSymbolAddress(&po1, sWo1); cudaGetSymbolAddress(&po2, sWo2);
    cudaGetSymbolAddress(&po3, sWo3);

    cudaFuncSetAttribute(attn_kernel, cudaFuncAttributeMaxDynamicSharedMemorySize, ATTN_SMEM);
    cudaFuncSetAttribute(qkv_mma, cudaFuncAttributeMaxDynamicSharedMemorySize, MMA_SMEM);
    cudaFuncSetAttribute(o_mma,   cudaFuncAttributeMaxDynamicSharedMemorySize, MMA_SMEM);

    // splits: all 3-way
    int nX = ROWS * HID, nWq = HID * HID, nWkv = KVDIM * HID;
    split_kernel<<<(nX + 255) / 256, 256>>>(X, (__nv_bfloat16*)px1, (__nv_bfloat16*)px2,
                                            (__nv_bfloat16*)px3, nX);
    split_kernel<<<(nWq + 255) / 256, 256>>>(Wq, (__nv_bfloat16*)pq1, (__nv_bfloat16*)pq2,
                                             (__nv_bfloat16*)pq3, nWq);
    split_kernel<<<(nWkv + 255) / 256, 256>>>(Wk, (__nv_bfloat16*)pk1, (__nv_bfloat16*)pk2,
                                              (__nv_bfloat16*)pk3, nWkv);
    split_kernel<<<(nWkv + 255) / 256, 256>>>(Wv, (__nv_bfloat16*)pv1, (__nv_bfloat16*)pv2,
                                              (__nv_bfloat16*)pv3, nWkv);
    split_kernel<<<(nWq + 255) / 256, 256>>>(Wo, (__nv_bfloat16*)po1, (__nv_bfloat16*)po2,
                                             (__nv_bfloat16*)po3, nWq);

    qkv_mma<<<dim3(48, 16), 256, MMA_SMEM>>>(
        (const __nv_bfloat16*)px1, (const __nv_bfloat16*)px2, (const __nv_bfloat16*)px3,
        (const __nv_bfloat16*)pq1, (const __nv_bfloat16*)pq2, (const __nv_bfloat16*)pq3,
        (const __nv_bfloat16*)pk1, (const __nv_bfloat16*)pk2, (const __nv_bfloat16*)pk3,
        (const __nv_bfloat16*)pv1, (const __nv_bfloat16*)pv2, (const __nv_bfloat16*)pv3,
        (float*)pQ, (float*)pK, (float*)pV);

    quant_k_cols<<<KVDIM, 256>>>((float*)pK);
    quant_v_rows<<<ROWS, 256>>>((float*)pV);

    rope_kernel<<<(BATCH * SEQ * NH * 64 + 255) / 256, 256>>>((float*)pQ, NH);
    rope_kernel<<<(BATCH * SEQ * KVH * 64 + 255) / 256, 256>>>((float*)pK, KVH);

    attn_kernel<<<dim3(SEQ / 64, NH, BATCH), 256, ATTN_SMEM>>>(
        (const float*)pQ, (const float*)pK, (const float*)pV, (float*)pA);

    split_kernel<<<(nX + 255) / 256, 256>>>((const float*)pA, (__nv_bfloat16*)pa1,
                                            (__nv_bfloat16*)pa2, (__nv_bfloat16*)pa3, nX);
    o_mma<<<dim3(32, 16), 256, MMA_SMEM>>>(
        (const __nv_bfloat16*)pa1, (const __nv_bfloat16*)pa2, (const __nv_bfloat16*)pa3,
        (const __nv_bfloat16*)po1, (const __nv_bfloat16*)po2, (const __nv_bfloat16*)po3,
        out);
}

// round 15
// speedup vs baseline: 1.5535x; 1.1374x over previous
#include <cuda_runtime.h>
#include <cuda_bf16.h>
#include <cfloat>
#include <math.h>
#include <stdint.h>

// Problem constants
#define BATCH 2
#define SEQ 1024
#define HID 4096
#define NH 32
#define KVH 8
#define HD 128
#define ROWS (BATCH*SEQ)          // 2048
#define KVDIM (KVH*HD)            // 1024

// ---------------- scratch (static __device__, no allocation) ----------------
__device__ float g_Q[ROWS * HID];     // (b,s,32,128)
__device__ float g_K[ROWS * KVDIM];
__device__ float g_V[ROWS * KVDIM];
__device__ float g_A[ROWS * HID];     // attention output

// bf16 split operands
__device__ __nv_bfloat16 sX1[ROWS * HID], sX2[ROWS * HID], sX3[ROWS * HID];
__device__ __nv_bfloat16 sWq1[HID * HID], sWq2[HID * HID], sWq3[HID * HID];
__device__ __nv_bfloat16 sWk1[KVDIM * HID], sWk2[KVDIM * HID], sWk3[KVDIM * HID];
__device__ __nv_bfloat16 sWv1[KVDIM * HID], sWv2[KVDIM * HID], sWv3[KVDIM * HID];
__device__ __nv_bfloat16 sA1[ROWS * HID], sA2[ROWS * HID], sA3[ROWS * HID];
__device__ __nv_bfloat16 sWo1[HID * HID], sWo2[HID * HID], sWo3[HID * HID];

// ---------------- mma.sync / cp.async helpers (baseline PTX, sm_80+) --------
__device__ __forceinline__ uint32_t smem_u32(const void* p) {
    uint32_t a;
    asm("{ .reg .u64 t; cvta.to.shared.u64 t, %1; cvt.u32.u64 %0, t; }"
        : "=r"(a) : "l"(p));
    return a;
}

#define LDSM_X4(r0, r1, r2, r3, addr) \
    asm volatile("ldmatrix.sync.aligned.m8n8.x4.shared.b16 {%0,%1,%2,%3}, [%4];" \
                 : "=r"(r0), "=r"(r1), "=r"(r2), "=r"(r3) : "r"(addr))

__device__ __forceinline__ void mma16816(float* c, const uint32_t* a,
                                         uint32_t b0, uint32_t b1)
{
    asm volatile(
        "mma.sync.aligned.m16n8k16.row.col.f32.bf16.bf16.f32 "
        "{%0,%1,%2,%3}, {%4,%5,%6,%7}, {%8,%9}, {%0,%1,%2,%3};"
        : "+f"(c[0]), "+f"(c[1]), "+f"(c[2]), "+f"(c[3])
        : "r"(a[0]), "r"(a[1]), "r"(a[2]), "r"(a[3]), "r"(b0), "r"(b1));
}

#define CP_ASYNC16(saddr, gptr) \
    asm volatile("cp.async.cg.shared.global [%0], [%1], 16;" \
                 :: "r"(saddr), "l"(gptr) : "memory")
#define CP_COMMIT() asm volatile("cp.async.commit_group;" ::: "memory")
#define CP_WAIT(n)  asm volatile("cp.async.wait_group %0;" :: "n"(n) : "memory")

// ---------------- split-bf16 GEMM via mma.sync: C[128,128] = A * B^T --------
// terms==3: a1b1 + a1b2 + a2b1            (error ~1e-5, smooth paths only)
// terms==6: + a2b2 + a1b3 + a3b1          (exact to 2^-27, for K/V)
// TC accumulation is non-IEEE: drain into fp32 master accumulator (IEEE RN)
// after every K-chunk. Loads use cp.async double-buffering so global/L2
// latency overlaps the mma phase of the previous chunk.
#define LDT 40                        // smem tile stride in bf16 (80B, 16B-mult)
#define CH_K 32                       // k per chunk
#define TILE_ELEMS (128 * LDT)        // per tile slot, bf16
#define MMA_SMEM (12 * TILE_ELEMS * 2) // double-buffered: 122880 bytes

__device__ __forceinline__ void mma_gemm_body(
    const __nv_bfloat16* A1, const __nv_bfloat16* A2, const __nv_bfloat16* A3,
    const __nv_bfloat16* B1, const __nv_bfloat16* B2, const __nv_bfloat16* B3,
    float* C, int ldc, int colbase, int row0, int K, int terms)
{
    extern __shared__ __nv_bfloat16 sm[];
    uint32_t smbase = smem_u32(sm);
    int tid = threadIdx.x;
    int wid = tid >> 5, lane = tid & 31;
    int wy = wid >> 1, wx = wid & 1;          // warp tile: rows wy*32, cols wx*64
    int nAB = (terms == 6) ? 3 : 2;
    const __nv_bfloat16* Ap[3] = {A1, A2, A3};
    const __nv_bfloat16* Bp[3] = {B1, B2, B3};
    const int ta[6] = {0, 0, 1, 1, 0, 2};
    const int tb[6] = {0, 1, 0, 1, 2, 0};

    float acc[2][8][4];    // TC accumulator (short chains only)
    float facc[2][8][4];   // fp32 master accumulator (IEEE RN adds)
#pragma unroll
    for (int mt = 0; mt < 2; mt++)
#pragma unroll
        for (int nt = 0; nt < 8; nt++)
#pragma unroll
            for (int e = 0; e < 4; e++) { acc[mt][nt][e] = 0.f; facc[mt][nt][e] = 0.f; }

    // per-lane ldmatrix address components (element units within a tile)
    int a_row = ((lane >> 3) & 1) * 8 + (lane & 7);  // + R
    int a_col = (lane >> 4) * 8;                      // + ks
    int b_row = (lane >> 4) * 8 + (lane & 7);         // + Nb
    int b_col = ((lane >> 3) & 1) * 8;                // + ks

    // per-thread load coordinates (2 x uint4 per tile slot)
    int r0l = tid >> 2, q0l = (tid & 3) * 8;
    int r1l = (tid + 256) >> 2, q1l = ((tid + 256) & 3) * 8;

    int nchunks = K / CH_K;

    // preload chunk 0 into buffer 0
#pragma unroll
    for (int t = 0; t < 3; t++) {
        if (t >= nAB) break;
        uint32_t dA = smbase + (uint32_t)(t * TILE_ELEMS) * 2;
        uint32_t dB = smbase + (uint32_t)((3 + t) * TILE_ELEMS) * 2;
        CP_ASYNC16(dA + (uint32_t)(r0l * LDT + q0l) * 2, Ap[t] + (size_t)r0l * K + q0l);
        CP_ASYNC16(dA + (uint32_t)(r1l * LDT + q1l) * 2, Ap[t] + (size_t)r1l * K + q1l);
        CP_ASYNC16(dB + (uint32_t)(r0l * LDT + q0l) * 2, Bp[t] + (size_t)r0l * K + q0l);
        CP_ASYNC16(dB + (uint32_t)(r1l * LDT + q1l) * 2, Bp[t] + (size_t)r1l * K + q1l);
    }
    CP_COMMIT();

    for (int ch = 0; ch < nchunks; ch++) {
        int p = ch & 1;
        if (ch > 0) __syncthreads();          // prev compute done reading buf p^1
        if (ch + 1 < nchunks) {
            int kn = (ch + 1) * CH_K;
            uint32_t bufo = (uint32_t)((p ^ 1) * 6) * TILE_ELEMS * 2;
#pragma unroll
            for (int t = 0; t < 3; t++) {
                if (t >= nAB) break;
                uint32_t dA = smbase + bufo + (uint32_t)(t * TILE_ELEMS) * 2;
                uint32_t dB = smbase + bufo + (uint32_t)((3 + t) * TILE_ELEMS) * 2;
                CP_ASYNC16(dA + (uint32_t)(r0l * LDT + q0l) * 2, Ap[t] + (size_t)r0l * K + kn + q0l);
                CP_ASYNC16(dA + (uint32_t)(r1l * LDT + q1l) * 2, Ap[t] + (size_t)r1l * K + kn + q1l);
                CP_ASYNC16(dB + (uint32_t)(r0l * LDT + q0l) * 2, Bp[t] + (size_t)r0l * K + kn + q0l);
                CP_ASYNC16(dB + (uint32_t)(r1l * LDT + q1l) * 2, Bp[t] + (size_t)r1l * K + kn + q1l);
            }
            CP_COMMIT();
            CP_WAIT(1);                        // chunk ch's copies complete
        } else {
            CP_WAIT(0);
        }
        __syncthreads();

        uint32_t bufc = (uint32_t)(p * 6) * TILE_ELEMS * 2;
        for (int tt = 0; tt < terms; tt++) {
            uint32_t aBase = smbase + bufc + (uint32_t)ta[tt] * TILE_ELEMS * 2;
            uint32_t bBase = smbase + bufc + (uint32_t)(3 + tb[tt]) * TILE_ELEMS * 2;
#pragma unroll
            for (int ks = 0; ks < CH_K; ks += 16) {
                uint32_t a[2][4];
#pragma unroll
                for (int mt = 0; mt < 2; mt++) {
                    int R = wy * 32 + mt * 16;
                    uint32_t addr = aBase +
                        (uint32_t)(((R + a_row) * LDT) + ks + a_col) * 2;
                    LDSM_X4(a[mt][0], a[mt][1], a[mt][2], a[mt][3], addr);
                }
                uint32_t b[4][4];
#pragma unroll
                for (int np = 0; np < 4; np++) {
                    int Nb = wx * 64 + np * 16;
                    uint32_t addr = bBase +
                        (uint32_t)(((Nb + b_row) * LDT) + ks + b_col) * 2;
                    LDSM_X4(b[np][0], b[np][1], b[np][2], b[np][3], addr);
                }
#pragma unroll
                for (int mt = 0; mt < 2; mt++)
#pragma unroll
                    for (int np = 0; np < 4; np++) {
                        mma16816(acc[mt][np * 2 + 0], a[mt], b[np][0], b[np][1]);
                        mma16816(acc[mt][np * 2 + 1], a[mt], b[np][2], b[np][3]);
                    }
            }
        }

        // drain TC accumulator into fp32 master accumulator (IEEE RN adds)
#pragma unroll
        for (int mt = 0; mt < 2; mt++)
#pragma unroll
            for (int nt = 0; nt < 8; nt++)
#pragma unroll
                for (int e = 0; e < 4; e++) {
                    facc[mt][nt][e] += acc[mt][nt][e];
                    acc[mt][nt][e] = 0.f;
                }
    }

    // epilogue: c0,c1 -> (row, col..col+1); c2,c3 -> (row+8, ..)
#pragma unroll
    for (int mt = 0; mt < 2; mt++) {
        int row = row0 + wy * 32 + mt * 16 + (lane >> 2);
#pragma unroll
        for (int nt = 0; nt < 8; nt++) {
            int col = colbase + wx * 64 + nt * 8 + 2 * (lane & 3);
            float* p0 = C + (size_t)row * ldc + col;
            p0[0] = facc[mt][nt][0];
            p0[1] = facc[mt][nt][1];
            float* p1 = p0 + (size_t)8 * ldc;
            p1[0] = facc[mt][nt][2];
            p1[1] = facc[mt][nt][3];
        }
    }
}

// Fused QKV: grid (48,16); bx<32 Q (3 terms), <40 K (6), else V (6)
__global__ __launch_bounds__(256, 1) void qkv_mma(
    const __nv_bfloat16* x1, const __nv_bfloat16* x2, const __nv_bfloat16* x3,
    const __nv_bfloat16* wq1, const __nv_bfloat16* wq2, const __nv_bfloat16* wq3,
    const __nv_bfloat16* wk1, const __nv_bfloat16* wk2, const __nv_bfloat16* wk3,
    const __nv_bfloat16* wv1, const __nv_bfloat16* wv2, const __nv_bfloat16* wv3,
    float* Qo, float* Ko, float* Vo)
{
    int bx = blockIdx.x, by = blockIdx.y;
    int row0 = by * 128;
    size_t aoff = (size_t)row0 * HID;
    if (bx < 32) {
        size_t boff = (size_t)bx * 128 * HID;
        mma_gemm_body(x1 + aoff, x2 + aoff, x3 + aoff,
                      wq1 + boff, wq2 + boff, wq3 + boff,
                      Qo, HID, bx * 128, row0, HID, 3);
    } else if (bx < 40) {
        int cb = bx - 32;
        size_t boff = (size_t)cb * 128 * HID;
        mma_gemm_body(x1 + aoff, x2 + aoff, x3 + aoff,
                      wk1 + boff, wk2 + boff, wk3 + boff,
                      Ko, KVDIM, cb * 128, row0, HID, 6);
    } else {
        int cb = bx - 40;
        size_t boff = (size_t)cb * 128 * HID;
        mma_gemm_body(x1 + aoff, x2 + aoff, x3 + aoff,
                      wv1 + boff, wv2 + boff, wv3 + boff,
                      Vo, KVDIM, cb * 128, row0, HID, 6);
    }
}

__global__ __launch_bounds__(256, 1) void o_mma(
    const __nv_bfloat16* a1, const __nv_bfloat16* a2, const __nv_bfloat16* a3,
    const __nv_bfloat16* w1, const __nv_bfloat16* w2, const __nv_bfloat16* w3,
    float* C)
{
    int bx = blockIdx.x, by = blockIdx.y;
    int row0 = by * 128;
    size_t aoff = (size_t)row0 * HID;
    size_t boff = (size_t)bx * 128 * HID;
    mma_gemm_body(a1 + aoff, a2 + aoff, a3 + aoff,
                  w1 + boff, w2 + boff, w3 + boff,
                  C, HID, bx * 128, row0, HID, 3);
}

// ---------------- split fp32 -> bf16 hi/lo/lo2 ------------------------------
__global__ void split_kernel(const float* __restrict__ in,
                             __nv_bfloat16* __restrict__ o1,
                             __nv_bfloat16* __restrict__ o2,
                             __nv_bfloat16* __restrict__ o3,
                             int n)
{
    int i = blockIdx.x * blockDim.x + threadIdx.x;
    if (i >= n) return;
    float v = in[i];
    __nv_bfloat16 b1 = __float2bfloat16_rn(v);
    float r = v - __bfloat162float(b1);
    __nv_bfloat16 b2 = __float2bfloat16_rn(r);
    float r2 = r - __bfloat162float(b2);
    o1[i] = b1; o2[i] = b2;
    o3[i] = __float2bfloat16_rn(r2);
}

// ---------------- fake_quant_sparse: K (per-column, n=2048) -----------------
__global__ __launch_bounds__(256) void quant_k_cols(float* __restrict__ Kd)
{
    const int n = 2048;
    __shared__ float s[2048];
    __shared__ float red[256];
    int col = blockIdx.x;
    int tid = threadIdx.x;
    float vals[8];
#pragma unroll
    for (int i = 0; i < 8; i++) {
        float v = Kd[(size_t)(i * 256 + tid) * KVDIM + col];
        vals[i] = v;
        s[i * 256 + tid] = v;
    }
    __syncthreads();
    for (int k = 2; k <= n; k <<= 1) {
        for (int j = k >> 1; j > 0; j >>= 1) {
            for (int t = tid; t < n; t += 256) {
                int ixj = t ^ j;
                if (ixj > t) {
                    float a = s[t], b = s[ixj];
                    bool up = ((t & k) == 0);
                    if ((a > b) == up) { s[t] = b; s[ixj] = a; }
                }
            }
            __syncthreads();
        }
    }
    float tq = 1.0f - (1.0f - 0.999f) / 2.0f;
    float plo = (1.0f - tq) * (n - 1);
    float phi = tq * (n - 1);
    int ilo = (int)plo, ihi = (int)phi;
    float flo = plo - ilo, fhi = phi - ihi;
    float lower = s[ilo] + flo * (s[ilo + 1] - s[ilo]);
    float upper = s[ihi] + fhi * (s[ihi + 1] - s[ihi]);
    float med = s[(n - 1) / 2];
    float mn = FLT_MAX, mx = -FLT_MAX;
#pragma unroll
    for (int i = 0; i < 8; i++) {
        float x = vals[i];
        bool mask = (x <= lower) || (x >= upper);
        float tv = mask ? med : x;
        mn = fminf(mn, tv);
        mx = fmaxf(mx, tv);
    }
    red[tid] = mn; __syncthreads();
    for (int off = 128; off; off >>= 1) {
        if (tid < off) red[tid] = fminf(red[tid], red[tid + off]);
        __syncthreads();
    }
    mn = red[0]; __syncthreads();
    red[tid] = mx; __syncthreads();
    for (int off = 128; off; off >>= 1) {
        if (tid < off) red[tid] = fmaxf(red[tid], red[tid + off]);
        __syncthreads();
    }
    mx = red[0];
    float qx = 15.0f / (mx - mn);
    float offn = mn * qx;
#pragma unroll
    for (int i = 0; i < 8; i++) {
        float x = vals[i];
        bool mask = (x <= lower) || (x >= upper);
        float out;
        if (mask) out = x;
        else {
            float q = rintf(qx * x - offn);
            q = fminf(fmaxf(q, 0.f), 15.f);
            out = (q + offn) / qx;
        }
        if (!isfinite(out)) out = 0.f;
        Kd[(size_t)(i * 256 + tid) * KVDIM + col] = out;
    }
}

// ---------------- fake_quant_sparse: V (per-row, n=1024) --------------------
__global__ __launch_bounds__(256) void quant_v_rows(float* __restrict__ Vd)
{
    const int n = 1024;
    __shared__ float s[1024];
    __shared__ float red[256];
    int row = blockIdx.x;
    int tid = threadIdx.x;
    float* rp = Vd + (size_t)row * KVDIM;
    float vals[4];
#pragma unroll
    for (int i = 0; i < 4; i++) {
        float v = rp[i * 256 + tid];
        vals[i] = v;
        s[i * 256 + tid] = v;
    }
    __syncthreads();
    for (int k = 2; k <= n; k <<= 1) {
        for (int j = k >> 1; j > 0; j >>= 1) {
            for (int t = tid; t < n; t += 256) {
                int ixj = t ^ j;
                if (ixj > t) {
                    float a = s[t], b = s[ixj];
                    bool up = ((t & k) == 0);
                    if ((a > b) == up) { s[t] = b; s[ixj] = a; }
                }
            }
            __syncthreads();
        }
    }
    float tq = 1.0f - (1.0f - 0.999f) / 2.0f;
    float plo = (1.0f - tq) * (n - 1);
    float phi = tq * (n - 1);
    int ilo = (int)plo, ihi = (int)phi;
    float flo = plo - ilo, fhi = phi - ihi;
    float lower = s[ilo] + flo * (s[ilo + 1] - s[ilo]);
    float upper = s[ihi] + fhi * (s[ihi + 1] - s[ihi]);
    float med = s[(n - 1) / 2];
    float mn = FLT_MAX, mx = -FLT_MAX;
#pragma unroll
    for (int i = 0; i < 4; i++) {
        float x = vals[i];
        bool mask = (x <= lower) || (x >= upper);
        float tv = mask ? med : x;
        mn = fminf(mn, tv);
        mx = fmaxf(mx, tv);
    }
    red[tid] = mn; __syncthreads();
    for (int off = 128; off; off >>= 1) {
        if (tid < off) red[tid] = fminf(red[tid], red[tid + off]);
        __syncthreads();
    }
    mn = red[0]; __syncthreads();
    red[tid] = mx; __syncthreads();
    for (int off = 128; off; off >>= 1) {
        if (tid < off) red[tid] = fmaxf(red[tid], red[tid + off]);
        __syncthreads();
    }
    mx = red[0];
    float qx = 15.0f / (mx - mn);
    float offn = mn * qx;
#pragma unroll
    for (int i = 0; i < 4; i++) {
        float x = vals[i];
        bool mask = (x <= lower) || (x >= upper);
        float out;
        if (mask) out = x;
        else {
            float q = rintf(qx * x - offn);
            q = fminf(fmaxf(q, 0.f), 15.f);
            out = (q + offn) / qx;
        }
        if (!isfinite(out)) out = 0.f;
        rp[i * 256 + tid] = out;
    }
}

// ---------------- RoPE ------------------------------------------------------
__global__ void rope_kernel(float* __restrict__ X, int nheads)
{
    int idx = blockIdx.x * blockDim.x + threadIdx.x;
    int total = BATCH * SEQ * nheads * 64;
    if (idx >= total) return;
    int i = idx & 63;
    int rest = idx >> 6;
    int sh = rest / nheads;
    int spos = sh & (SEQ - 1);
    double expo = (double)(2 * i) / 128.0;
    float invf = (float)exp(-expo * 9.210340371976184);
    float f = (float)spos * invf;
    double fd = (double)f;
    double r = fd - rint(fd * 0.15915494309189535) * 6.283185307179586;
    float rf = (float)r;
    float c = cosf(rf), sn = sinf(rf);
    size_t base = (size_t)rest * 128 + i;
    float lo = X[base], hi = X[base + 64];
    X[base]      = lo * c - hi * sn;
    X[base + 64] = hi * c + lo * sn;
}

// ---------------- causal flash attention, fp32 ------------------------------
#define QST 68
#define ATTN_SMEM ((128*QST + 128*QST + 64*128 + 64*QST) * 4)

__global__ __launch_bounds__(256) void attn_kernel(const float* __restrict__ Q,
                                                   const float* __restrict__ Km,
                                                   const float* __restrict__ Vm,
                                                   float* __restrict__ O)
{
    extern __shared__ float smb[];
    float* Qst = smb;
    float* Kst = Qst + 128 * QST;
    float* Vs  = Kst + 128 * QST;
    float* Sst = Vs + 64 * 128;
    int qt = (SEQ / 64 - 1) - blockIdx.x;
    int h = blockIdx.y, b = blockIdx.z;
    int kvh = h >> 2;
    int tid = threadIdx.x;
    int tx = tid & 15, ty = tid >> 4;
    int q0 = qt * 64;

    for (int t = tid; t < 64 * 32; t += 256) {
        int rr = t >> 5, cc = (t & 31) << 2;
        float4 v = *(const float4*)&Q[(((size_t)(b * SEQ + q0 + rr)) * NH + h) * HD + cc];
        Qst[(cc + 0) * QST + rr] = v.x;
        Qst[(cc + 1) * QST + rr] = v.y;
        Qst[(cc + 2) * QST + rr] = v.z;
        Qst[(cc + 3) * QST + rr] = v.w;
    }

    float m_run[4], l_run[4], acc[4][8];
#pragma unroll
    for (int i = 0; i < 4; i++) {
        m_run[i] = -FLT_MAX; l_run[i] = 0.f;
#pragma unroll
        for (int j = 0; j < 8; j++) acc[i][j] = 0.f;
    }
    const float scale = 0.08838834764831845f;

    for (int jt = 0; jt <= qt; jt++) {
        int k0 = jt * 64;
        __syncthreads();
        for (int t = tid; t < 64 * 32; t += 256) {
            int rr = t >> 5, cc = (t & 31) << 2;
            size_t gi = (((size_t)(b * SEQ + k0 + rr)) * KVH + kvh) * HD + cc;
            float4 kv = *(const float4*)&Km[gi];
            Kst[(cc + 0) * QST + rr] = kv.x;
            Kst[(cc + 1) * QST + rr] = kv.y;
            Kst[(cc + 2) * QST + rr] = kv.z;
            Kst[(cc + 3) * QST + rr] = kv.w;
            *(float4*)&Vs[rr * 128 + cc] = *(const float4*)&Vm[gi];
        }
        __syncthreads();

        float s4[4][4];
#pragma unroll
        for (int i = 0; i < 4; i++)
#pragma unroll
            for (int j = 0; j < 4; j++) s4[i][j] = 0.f;
#pragma unroll 4
        for (int d = 0; d < 128; d++) {
            float4 qv = *(const float4*)&Qst[d * QST + ty * 4];
            float4 kv = *(const float4*)&Kst[d * QST + tx * 4];
            float qa[4] = {qv.x, qv.y, qv.z, qv.w};
            float ka[4] = {kv.x, kv.y, kv.z, kv.w};
#pragma unroll
            for (int i = 0; i < 4; i++)
#pragma unroll
                for (int j = 0; j < 4; j++)
                    s4[i][j] = fmaf(qa[i], ka[j], s4[i][j]);
        }
#pragma unroll
        for (int i = 0; i < 4; i++) {
            int qi = q0 + ty * 4 + i;
#pragma unroll
            for (int j = 0; j < 4; j++) {
                int kj = k0 + tx * 4 + j;
                float sv = s4[i][j] * scale;
                s4[i][j] = (kj > qi) ? -FLT_MAX : sv;
            }
        }
#pragma unroll
        for (int i = 0; i < 4; i++) {
            float mloc = fmaxf(fmaxf(s4[i][0], s4[i][1]), fmaxf(s4[i][2], s4[i][3]));
            mloc = fmaxf(mloc, __shfl_xor_sync(0xffffffffu, mloc, 8, 16));
            mloc = fmaxf(mloc, __shfl_xor_sync(0xffffffffu, mloc, 4, 16));
            mloc = fmaxf(mloc, __shfl_xor_sync(0xffffffffu, mloc, 2, 16));
            mloc = fmaxf(mloc, __shfl_xor_sync(0xffffffffu, mloc, 1, 16));
            float mn = fmaxf(m_run[i], mloc);
            float corr = expf(m_run[i] - mn);
            m_run[i] = mn;
            float sloc = 0.f;
#pragma unroll
            for (int j = 0; j < 4; j++) {
                float p = expf(s4[i][j] - mn);
                s4[i][j] = p;
                sloc += p;
            }
            sloc += __shfl_xor_sync(0xffffffffu, sloc, 8, 16);
            sloc += __shfl_xor_sync(0xffffffffu, sloc, 4, 16);
            sloc += __shfl_xor_sync(0xffffffffu, sloc, 2, 16);
            sloc += __shfl_xor_sync(0xffffffffu, sloc, 1, 16);
            l_run[i] = l_run[i] * corr + sloc;
#pragma unroll
            for (int j = 0; j < 8; j++) acc[i][j] *= corr;
        }
#pragma unroll
        for (int i = 0; i < 4; i++)
#pragma unroll
            for (int j = 0; j < 4; j++)
                Sst[(tx * 4 + j) * QST + (ty * 4 + i)] = s4[i][j];
        __syncthreads();
#pragma unroll 2
        for (int c = 0; c < 64; c++) {
            float4 pv = *(const float4*)&Sst[c * QST + ty * 4];
            float4 v0 = *(const float4*)&Vs[c * 128 + tx * 8];
            float4 v1 = *(const float4*)&Vs[c * 128 + tx * 8 + 4];
            float p[4] = {pv.x, pv.y, pv.z, pv.w};
            float vv[8] = {v0.x, v0.y, v0.z, v0.w, v1.x, v1.y, v1.z, v1.w};
#pragma unroll
            for (int i = 0; i < 4; i++)
#pragma unroll
                for (int j = 0; j < 8; j++)
                    acc[i][j] = fmaf(p[i], vv[j], acc[i][j]);
        }
    }
#pragma unroll
    for (int i = 0; i < 4; i++) {
        float inv = 1.0f / l_run[i];
        int row = q0 + ty * 4 + i;
        float* op = O + (((size_t)(b * SEQ + row)) * NH + h) * HD + tx * 8;
        *(float4*)op       = make_float4(acc[i][0] * inv, acc[i][1] * inv, acc[i][2] * inv, acc[i][3] * inv);
        *(float4*)(op + 4) = make_float4(acc[i][4] * inv, acc[i][5] * inv, acc[i][6] * inv, acc[i][7] * inv);
    }
}

// ---------------- launch ----------------------------------------------------
extern "C" void kernel_launch(void* const* d_in, const int* in_sizes, int n_in,
                              void* d_out, int out_size)
{
    (void)in_sizes; (void)n_in; (void)out_size;
    const float* X  = (const float*)d_in[0];
    const float* Wq = (const float*)d_in[1];
    const float* Wk = (const float*)d_in[2];
    const float* Wv = (const float*)d_in[3];
    const float* Wo = (const float*)d_in[4];
    float* out = (float*)d_out;

    void *pQ, *pK, *pV, *pA;
    cudaGetSymbolAddress(&pQ, g_Q);
    cudaGetSymbolAddress(&pK, g_K);
    cudaGetSymbolAddress(&pV, g_V);
    cudaGetSymbolAddress(&pA, g_A);
    void *px1, *px2, *px3, *pq1, *pq2, *pq3, *pk1, *pk2, *pk3;
    void *pv1, *pv2, *pv3, *pa1, *pa2, *pa3, *po1, *po2, *po3;
    cudaGetSymbolAddress(&px1, sX1); cudaGetSymbolAddress(&px2, sX2);
    cudaGetSymbolAddress(&px3, sX3);
    cudaGetSymbolAddress(&pq1, sWq1); cudaGetSymbolAddress(&pq2, sWq2);
    cudaGetSymbolAddress(&pq3, sWq3);
    cudaGetSymbolAddress(&pk1, sWk1); cudaGetSymbolAddress(&pk2, sWk2);
    cudaGetSymbolAddress(&pk3, sWk3);
    cudaGetSymbolAddress(&pv1, sWv1); cudaGetSymbolAddress(&pv2, sWv2);
    cudaGetSymbolAddress(&pv3, sWv3);
    cudaGetSymbolAddress(&pa1, sA1);  cudaGetSymbolAddress(&pa2, sA2);
    cudaGetSymbolAddress(&pa3, sA3);
    cudaGetSymbolAddress(&po1, sWo1); cudaGetSymbolAddress(&po2, sWo2);
    cudaGetSymbolAddress(&po3, sWo3);

    cudaFuncSetAttribute(attn_kernel, cudaFuncAttributeMaxDynamicSharedMemorySize, ATTN_SMEM);
    cudaFuncSetAttribute(qkv_mma, cudaFuncAttributeMaxDynamicSharedMemorySize, MMA_SMEM);
    cudaFuncSetAttribute(o_mma,   cudaFuncAttributeMaxDynamicSharedMemorySize, MMA_SMEM);

    // splits: all 3-way
    int nX = ROWS * HID, nWq = HID * HID, nWkv = KVDIM * HID;
    split_kernel<<<(nX + 255) / 256, 256>>>(X, (__nv_bfloat16*)px1, (__nv_bfloat16*)px2,
                                            (__nv_bfloat16*)px3, nX);
    split_kernel<<<(nWq + 255) / 256, 256>>>(Wq, (__nv_bfloat16*)pq1, (__nv_bfloat16*)pq2,
                                             (__nv_bfloat16*)pq3, nWq);
    split_kernel<<<(nWkv + 255) / 256, 256>>>(Wk, (__nv_bfloat16*)pk1, (__nv_bfloat16*)pk2,
                                              (__nv_bfloat16*)pk3, nWkv);
    split_kernel<<<(nWkv + 255) / 256, 256>>>(Wv, (__nv_bfloat16*)pv1, (__nv_bfloat16*)pv2,
                                              (__nv_bfloat16*)pv3, nWkv);
    split_kernel<<<(nWq + 255) / 256, 256>>>(Wo, (__nv_bfloat16*)po1, (__nv_bfloat16*)po2,
                                             (__nv_bfloat16*)po3, nWq);

    qkv_mma<<<dim3(48, 16), 256, MMA_SMEM>>>(
        (const __nv_bfloat16*)px1, (const __nv_bfloat16*)px2, (const __nv_bfloat16*)px3,
        (const __nv_bfloat16*)pq1, (const __nv_bfloat16*)pq2, (const __nv_bfloat16*)pq3,
        (const __nv_bfloat16*)pk1, (const __nv_bfloat16*)pk2, (const __nv_bfloat16*)pk3,
        (const __nv_bfloat16*)pv1, (const __nv_bfloat16*)pv2, (const __nv_bfloat16*)pv3,
        (float*)pQ, (float*)pK, (float*)pV);

    quant_k_cols<<<KVDIM, 256>>>((float*)pK);
    quant_v_rows<<<ROWS, 256>>>((float*)pV);

    rope_kernel<<<(BATCH * SEQ * NH * 64 + 255) / 256, 256>>>((float*)pQ, NH);
    rope_kernel<<<(BATCH * SEQ * KVH * 64 + 255) / 256, 256>>>((float*)pK, KVH);

    attn_kernel<<<dim3(SEQ / 64, NH, BATCH), 256, ATTN_SMEM>>>(
        (const float*)pQ, (const float*)pK, (const float*)pV, (float*)pA);

    split_kernel<<<(nX + 255) / 256, 256>>>((const float*)pA, (__nv_bfloat16*)pa1,
                                            (__nv_bfloat16*)pa2, (__nv_bfloat16*)pa3, nX);
    o_mma<<<dim3(32, 16), 256, MMA_SMEM>>>(
        (const __nv_bfloat16*)pa1, (const __nv_bfloat16*)pa2, (const __nv_bfloat16*)pa3,
        (const __nv_bfloat16*)po1, (const __nv_bfloat16*)po2, (const __nv_bfloat16*)po3,
        out);
}